// round 1
// baseline (speedup 1.0000x reference)
#include <cuda_runtime.h>
#include <cuda_bf16.h>
#include <math_constants.h>

// Problem constants
#define BB 4
#define NN 2048
#define DIN 1024
#define DOUT 1024
#define NH 16
#define HD 64
#define MTOT (BB * NN)          // 8192 rows

// ---------------- scratch (device globals; no allocation allowed) -----------
__device__ float g_Q[MTOT * DOUT];
__device__ float g_K[MTOT * DOUT];
__device__ float g_V[MTOT * DOUT];
__device__ float g_C[MTOT * DOUT];
__device__ int   g_len[BB];

// ---------------- per-batch valid length from right-padding mask ------------
__global__ void len_kernel(const int* __restrict__ mask) {
    int b = blockIdx.x;
    int s = 0;
    for (int i = threadIdx.x; i < NN; i += 256) s += mask[b * NN + i];
    __shared__ int sh[256];
    sh[threadIdx.x] = s;
    __syncthreads();
    for (int off = 128; off; off >>= 1) {
        if (threadIdx.x < off) sh[threadIdx.x] += sh[threadIdx.x + off];
        __syncthreads();
    }
    if (threadIdx.x == 0) g_len[b] = sh[0];
}

// ---------------- 128x128x16 tiled SGEMM: QKV projections --------------------
// C[z] = A @ W[z];  A: [MTOT, DIN] row-major, W: [DIN, DOUT] row-major.
// gridDim = (DOUT/128, MTOT/128, 3), 256 threads, 8x8 register tile.
__global__ __launch_bounds__(256) void qkv_gemm(const float* __restrict__ A,
                                                const float* __restrict__ W0,
                                                const float* __restrict__ W1,
                                                const float* __restrict__ W2) {
    const float* W = (blockIdx.z == 0) ? W0 : (blockIdx.z == 1) ? W1 : W2;
    float* C = (blockIdx.z == 0) ? g_Q : (blockIdx.z == 1) ? g_K : g_V;

    __shared__ float As[16][128];
    __shared__ float Bs[16][128];

    const int tid = threadIdx.x;
    const int bm = blockIdx.y * 128;
    const int bn = blockIdx.x * 128;
    const int tx = tid & 15;
    const int ty = tid >> 4;

    float acc[8][8];
#pragma unroll
    for (int i = 0; i < 8; i++)
#pragma unroll
        for (int j = 0; j < 8; j++) acc[i][j] = 0.f;

    for (int k0 = 0; k0 < DIN; k0 += 16) {
#pragma unroll
        for (int i = 0; i < 2; i++) {
            int idx = tid + i * 256;                 // 512 float4 for A tile
            int r = idx >> 2, c4 = (idx & 3) * 4;
            float4 v = *(const float4*)(A + (size_t)(bm + r) * DIN + k0 + c4);
            As[c4 + 0][r] = v.x; As[c4 + 1][r] = v.y;
            As[c4 + 2][r] = v.z; As[c4 + 3][r] = v.w;
        }
#pragma unroll
        for (int i = 0; i < 2; i++) {
            int idx = tid + i * 256;                 // 512 float4 for B tile
            int kr = idx >> 5, c4 = (idx & 31) * 4;
            *(float4*)(&Bs[kr][c4]) =
                *(const float4*)(W + (size_t)(k0 + kr) * DOUT + bn + c4);
        }
        __syncthreads();
#pragma unroll
        for (int kk = 0; kk < 16; kk++) {
            float ra[8], rb[8];
            *(float4*)(ra)     = *(float4*)(&As[kk][ty * 8]);
            *(float4*)(ra + 4) = *(float4*)(&As[kk][ty * 8 + 4]);
            *(float4*)(rb)     = *(float4*)(&Bs[kk][tx * 8]);
            *(float4*)(rb + 4) = *(float4*)(&Bs[kk][tx * 8 + 4]);
#pragma unroll
            for (int i = 0; i < 8; i++)
#pragma unroll
                for (int j = 0; j < 8; j++) acc[i][j] += ra[i] * rb[j];
        }
        __syncthreads();
    }

#pragma unroll
    for (int i = 0; i < 8; i++) {
        int m = bm + ty * 8 + i;
#pragma unroll
        for (int j = 0; j < 8; j += 4) {
            int n = bn + tx * 8 + j;
            float4 v = make_float4(acc[i][j], acc[i][j + 1], acc[i][j + 2], acc[i][j + 3]);
            *(float4*)(C + (size_t)m * DOUT + n) = v;
        }
    }
}

// ---------------- output projection: out = g_C @ Wo + bo ---------------------
__global__ __launch_bounds__(256) void out_gemm(const float* __restrict__ Wo,
                                                const float* __restrict__ bo,
                                                float* __restrict__ Out) {
    __shared__ float As[16][128];
    __shared__ float Bs[16][128];

    const int tid = threadIdx.x;
    const int bm = blockIdx.y * 128;
    const int bn = blockIdx.x * 128;
    const int tx = tid & 15;
    const int ty = tid >> 4;

    float acc[8][8];
#pragma unroll
    for (int i = 0; i < 8; i++)
#pragma unroll
        for (int j = 0; j < 8; j++) acc[i][j] = 0.f;

    for (int k0 = 0; k0 < DOUT; k0 += 16) {
#pragma unroll
        for (int i = 0; i < 2; i++) {
            int idx = tid + i * 256;
            int r = idx >> 2, c4 = (idx & 3) * 4;
            float4 v = *(const float4*)(g_C + (size_t)(bm + r) * DOUT + k0 + c4);
            As[c4 + 0][r] = v.x; As[c4 + 1][r] = v.y;
            As[c4 + 2][r] = v.z; As[c4 + 3][r] = v.w;
        }
#pragma unroll
        for (int i = 0; i < 2; i++) {
            int idx = tid + i * 256;
            int kr = idx >> 5, c4 = (idx & 31) * 4;
            *(float4*)(&Bs[kr][c4]) =
                *(const float4*)(Wo + (size_t)(k0 + kr) * DOUT + bn + c4);
        }
        __syncthreads();
#pragma unroll
        for (int kk = 0; kk < 16; kk++) {
            float ra[8], rb[8];
            *(float4*)(ra)     = *(float4*)(&As[kk][ty * 8]);
            *(float4*)(ra + 4) = *(float4*)(&As[kk][ty * 8 + 4]);
            *(float4*)(rb)     = *(float4*)(&Bs[kk][tx * 8]);
            *(float4*)(rb + 4) = *(float4*)(&Bs[kk][tx * 8 + 4]);
#pragma unroll
            for (int i = 0; i < 8; i++)
#pragma unroll
                for (int j = 0; j < 8; j++) acc[i][j] += ra[i] * rb[j];
        }
        __syncthreads();
    }

#pragma unroll
    for (int i = 0; i < 8; i++) {
        int m = bm + ty * 8 + i;
#pragma unroll
        for (int j = 0; j < 8; j += 4) {
            int n = bn + tx * 8 + j;
            float4 v = make_float4(acc[i][j] + bo[n],
                                   acc[i][j + 1] + bo[n + 1],
                                   acc[i][j + 2] + bo[n + 2],
                                   acc[i][j + 3] + bo[n + 3]);
            *(float4*)(Out + (size_t)m * DOUT + n) = v;
        }
    }
}

// ---------------- flash attention (fp32, online softmax) ---------------------
// grid: (N/64, H, B), 256 threads. 4 threads per query row; each owns 16 dims.
#define BQ 64
#define BKT 64
__global__ __launch_bounds__(256) void attn_kernel() {
    __shared__ float Ks[BKT][HD];
    __shared__ float Vs[BKT][HD];

    const int b = blockIdx.z;
    const int h = blockIdx.y;
    const int q0 = blockIdx.x * BQ;
    const int len = g_len[b];
    const int tid = threadIdx.x;
    const int row = tid >> 2;     // 0..63 query row in tile
    const int sub = tid & 3;      // 0..3 -> dims [sub*16, sub*16+16)
    const int q_idx = q0 + row;

    // load q row slice into registers
    float qr[16];
    const float* qptr = g_Q + ((size_t)(b * NN + q_idx) * DOUT) + h * HD + sub * 16;
#pragma unroll
    for (int w = 0; w < 4; w++) *(float4*)(qr + 4 * w) = *(const float4*)(qptr + 4 * w);

    float o[16];
#pragma unroll
    for (int i = 0; i < 16; i++) o[i] = 0.f;
    float mrun = -CUDART_INF_F;
    float lrun = 0.f;

    const int kv_end = min(q0 + BQ, len);   // valid keys: j < len AND j <= q
    const float scale = 0.125f;             // 1/sqrt(64)

    for (int j0 = 0; j0 < kv_end; j0 += BKT) {
        // cooperative load of full 64x64 K and V tiles (always in-bounds: N%64==0)
#pragma unroll
        for (int i = 0; i < 4; i++) {
            int idx = tid + i * 256;            // 1024 float4 per matrix
            int r = idx >> 4, c4 = (idx & 15) * 4;
            size_t g = ((size_t)(b * NN + j0 + r) * DOUT) + h * HD + c4;
            *(float4*)(&Ks[r][c4]) = *(const float4*)(g_K + g);
            *(float4*)(&Vs[r][c4]) = *(const float4*)(g_V + g);
        }
        __syncthreads();

        const int jmax = min(BKT, kv_end - j0);
        for (int jj = 0; jj < jmax; jj++) {
            const int j = j0 + jj;
            float s = 0.f;
#pragma unroll
            for (int w = 0; w < 4; w++) {
                float4 kv = *(float4*)(&Ks[jj][sub * 16 + 4 * w]);
                s += qr[4 * w + 0] * kv.x + qr[4 * w + 1] * kv.y +
                     qr[4 * w + 2] * kv.z + qr[4 * w + 3] * kv.w;
            }
            // reduce partial dot across the 4-thread quad
            s += __shfl_xor_sync(0xffffffffu, s, 1);
            s += __shfl_xor_sync(0xffffffffu, s, 2);
            s *= scale;
            if (j > q_idx) s = -CUDART_INF_F;   // causal (j<len guaranteed by kv_end)

            float mnew = fmaxf(mrun, s);
            float corr = __expf(mrun - mnew);   // 0 when mrun = -inf
            float p = __expf(s - mnew);         // 0 when s masked
            lrun = lrun * corr + p;
#pragma unroll
            for (int w = 0; w < 4; w++) {
                float4 vv = *(float4*)(&Vs[jj][sub * 16 + 4 * w]);
                o[4 * w + 0] = o[4 * w + 0] * corr + p * vv.x;
                o[4 * w + 1] = o[4 * w + 1] * corr + p * vv.y;
                o[4 * w + 2] = o[4 * w + 2] * corr + p * vv.z;
                o[4 * w + 3] = o[4 * w + 3] * corr + p * vv.w;
            }
            mrun = mnew;
        }
        __syncthreads();
    }

    const float inv = 1.f / lrun;               // >=1 valid key always (j=0<=q, len>=N/2)
    float* optr = g_C + ((size_t)(b * NN + q_idx) * DOUT) + h * HD + sub * 16;
#pragma unroll
    for (int w = 0; w < 4; w++) {
        float4 v = make_float4(o[4 * w] * inv, o[4 * w + 1] * inv,
                               o[4 * w + 2] * inv, o[4 * w + 3] * inv);
        *(float4*)(optr + 4 * w) = v;
    }
}

// ---------------- launch ------------------------------------------------------
extern "C" void kernel_launch(void* const* d_in, const int* in_sizes, int n_in,
                              void* d_out, int out_size) {
    const float* x    = (const float*)d_in[0];
    const int*   mask = (const int*)d_in[1];
    const float* Wq   = (const float*)d_in[2];
    const float* Wk   = (const float*)d_in[3];
    const float* Wv   = (const float*)d_in[4];
    const float* Wo   = (const float*)d_in[5];
    const float* bo   = (const float*)d_in[6];
    float* out = (float*)d_out;

    len_kernel<<<BB, 256>>>(mask);

    dim3 gq(DOUT / 128, MTOT / 128, 3);
    qkv_gemm<<<gq, 256>>>(x, Wq, Wk, Wv);

    dim3 ga(NN / BQ, NH, BB);
    attn_kernel<<<ga, 256>>>();

    dim3 go(DOUT / 128, MTOT / 128, 1);
    out_gemm<<<go, 256>>>(Wo, bo, out);
}

// round 2
// speedup vs baseline: 2.2427x; 2.2427x over previous
#include <cuda_runtime.h>
#include <cuda_bf16.h>
#include <math_constants.h>

// Problem constants
#define BB 4
#define NN 2048
#define DIN 1024
#define DOUT 1024
#define NH 16
#define HD 64
#define MTOT (BB * NN)          // 8192 rows

// ---------------- scratch (device globals; no allocation allowed) -----------
__device__ float g_Q[MTOT * DOUT];
__device__ float g_K[MTOT * DOUT];
__device__ float g_V[MTOT * DOUT];
__device__ float g_C[MTOT * DOUT];
__device__ int   g_len[BB];

// ---------------- per-batch valid length from right-padding mask ------------
__global__ void len_kernel(const int* __restrict__ mask) {
    int b = blockIdx.x;
    int s = 0;
    for (int i = threadIdx.x; i < NN; i += 256) s += mask[b * NN + i];
    __shared__ int sh[256];
    sh[threadIdx.x] = s;
    __syncthreads();
    for (int off = 128; off; off >>= 1) {
        if (threadIdx.x < off) sh[threadIdx.x] += sh[threadIdx.x + off];
        __syncthreads();
    }
    if (threadIdx.x == 0) g_len[b] = sh[0];
}

// ---------------- 128x128x16 tiled SGEMM: QKV projections --------------------
__global__ __launch_bounds__(256) void qkv_gemm(const float* __restrict__ A,
                                                const float* __restrict__ W0,
                                                const float* __restrict__ W1,
                                                const float* __restrict__ W2) {
    const float* W = (blockIdx.z == 0) ? W0 : (blockIdx.z == 1) ? W1 : W2;
    float* C = (blockIdx.z == 0) ? g_Q : (blockIdx.z == 1) ? g_K : g_V;

    __shared__ float As[16][128];
    __shared__ float Bs[16][128];

    const int tid = threadIdx.x;
    const int bm = blockIdx.y * 128;
    const int bn = blockIdx.x * 128;
    const int tx = tid & 15;
    const int ty = tid >> 4;

    float acc[8][8];
#pragma unroll
    for (int i = 0; i < 8; i++)
#pragma unroll
        for (int j = 0; j < 8; j++) acc[i][j] = 0.f;

    for (int k0 = 0; k0 < DIN; k0 += 16) {
#pragma unroll
        for (int i = 0; i < 2; i++) {
            int idx = tid + i * 256;
            int r = idx >> 2, c4 = (idx & 3) * 4;
            float4 v = *(const float4*)(A + (size_t)(bm + r) * DIN + k0 + c4);
            As[c4 + 0][r] = v.x; As[c4 + 1][r] = v.y;
            As[c4 + 2][r] = v.z; As[c4 + 3][r] = v.w;
        }
#pragma unroll
        for (int i = 0; i < 2; i++) {
            int idx = tid + i * 256;
            int kr = idx >> 5, c4 = (idx & 31) * 4;
            *(float4*)(&Bs[kr][c4]) =
                *(const float4*)(W + (size_t)(k0 + kr) * DOUT + bn + c4);
        }
        __syncthreads();
#pragma unroll
        for (int kk = 0; kk < 16; kk++) {
            float ra[8], rb[8];
            *(float4*)(ra)     = *(float4*)(&As[kk][ty * 8]);
            *(float4*)(ra + 4) = *(float4*)(&As[kk][ty * 8 + 4]);
            *(float4*)(rb)     = *(float4*)(&Bs[kk][tx * 8]);
            *(float4*)(rb + 4) = *(float4*)(&Bs[kk][tx * 8 + 4]);
#pragma unroll
            for (int i = 0; i < 8; i++)
#pragma unroll
                for (int j = 0; j < 8; j++) acc[i][j] += ra[i] * rb[j];
        }
        __syncthreads();
    }

#pragma unroll
    for (int i = 0; i < 8; i++) {
        int m = bm + ty * 8 + i;
#pragma unroll
        for (int j = 0; j < 8; j += 4) {
            int n = bn + tx * 8 + j;
            float4 v = make_float4(acc[i][j], acc[i][j + 1], acc[i][j + 2], acc[i][j + 3]);
            *(float4*)(C + (size_t)m * DOUT + n) = v;
        }
    }
}

// ---------------- output projection: out = g_C @ Wo + bo ---------------------
__global__ __launch_bounds__(256) void out_gemm(const float* __restrict__ Wo,
                                                const float* __restrict__ bo,
                                                float* __restrict__ Out) {
    __shared__ float As[16][128];
    __shared__ float Bs[16][128];

    const int tid = threadIdx.x;
    const int bm = blockIdx.y * 128;
    const int bn = blockIdx.x * 128;
    const int tx = tid & 15;
    const int ty = tid >> 4;

    float acc[8][8];
#pragma unroll
    for (int i = 0; i < 8; i++)
#pragma unroll
        for (int j = 0; j < 8; j++) acc[i][j] = 0.f;

    for (int k0 = 0; k0 < DOUT; k0 += 16) {
#pragma unroll
        for (int i = 0; i < 2; i++) {
            int idx = tid + i * 256;
            int r = idx >> 2, c4 = (idx & 3) * 4;
            float4 v = *(const float4*)(g_C + (size_t)(bm + r) * DOUT + k0 + c4);
            As[c4 + 0][r] = v.x; As[c4 + 1][r] = v.y;
            As[c4 + 2][r] = v.z; As[c4 + 3][r] = v.w;
        }
#pragma unroll
        for (int i = 0; i < 2; i++) {
            int idx = tid + i * 256;
            int kr = idx >> 5, c4 = (idx & 31) * 4;
            *(float4*)(&Bs[kr][c4]) =
                *(const float4*)(Wo + (size_t)(k0 + kr) * DOUT + bn + c4);
        }
        __syncthreads();
#pragma unroll
        for (int kk = 0; kk < 16; kk++) {
            float ra[8], rb[8];
            *(float4*)(ra)     = *(float4*)(&As[kk][ty * 8]);
            *(float4*)(ra + 4) = *(float4*)(&As[kk][ty * 8 + 4]);
            *(float4*)(rb)     = *(float4*)(&Bs[kk][tx * 8]);
            *(float4*)(rb + 4) = *(float4*)(&Bs[kk][tx * 8 + 4]);
#pragma unroll
            for (int i = 0; i < 8; i++)
#pragma unroll
                for (int j = 0; j < 8; j++) acc[i][j] += ra[i] * rb[j];
        }
        __syncthreads();
    }

#pragma unroll
    for (int i = 0; i < 8; i++) {
        int m = bm + ty * 8 + i;
#pragma unroll
        for (int j = 0; j < 8; j += 4) {
            int n = bn + tx * 8 + j;
            float4 v = make_float4(acc[i][j] + bo[n],
                                   acc[i][j + 1] + bo[n + 1],
                                   acc[i][j + 2] + bo[n + 2],
                                   acc[i][j + 3] + bo[n + 3]);
            *(float4*)(Out + (size_t)m * DOUT + n) = v;
        }
    }
}

// ---------------- tile-GEMM flash attention (fp32) ---------------------------
// grid: (N/64, H, B), 256 threads as 16x16. Each thread: 4x4 of the 64x64
// score tile and 4 rows x 4 dims of the output tile.
// Dynamic smem: Qs[64][64], Kt[64][65] (dim-major), Vs[64][64], Pt[64][65] (key-major)
#define QS_OFF 0
#define KT_OFF 4096
#define VS_OFF (4096 + 4160)
#define PT_OFF (4096 + 4160 + 4096)
#define ATT_SMEM_FLOATS (4096 + 4160 + 4096 + 4160)
#define ATT_SMEM_BYTES (ATT_SMEM_FLOATS * 4)

__global__ __launch_bounds__(256) void attn_tile_kernel() {
    extern __shared__ float sm[];
    float* Qs = sm + QS_OFF;   // [row][dim]   64x64
    float* Kt = sm + KT_OFF;   // [dim][key]   64x65
    float* Vs = sm + VS_OFF;   // [key][dim]   64x64
    float* Pt = sm + PT_OFF;   // [key][row]   64x65

    const int b = blockIdx.z;
    const int h = blockIdx.y;
    const int q0 = blockIdx.x * 64;
    const int len = g_len[b];
    const int tid = threadIdx.x;
    const int tx = tid & 15;       // col group (keys / dims)
    const int ty = tid >> 4;       // row group (queries)

    // load Q tile [64 rows][64 dims]
#pragma unroll
    for (int i = 0; i < 4; i++) {
        int idx = tid + i * 256;
        int r = idx >> 4, c4 = (idx & 15) * 4;
        *(float4*)(Qs + r * 64 + c4) =
            *(const float4*)(g_Q + ((size_t)(b * NN + q0 + r) * DOUT) + h * HD + c4);
    }

    float O[16];
#pragma unroll
    for (int i = 0; i < 16; i++) O[i] = 0.f;
    float m[4], l[4];
#pragma unroll
    for (int i = 0; i < 4; i++) { m[i] = -CUDART_INF_F; l[i] = 0.f; }

    const int kv_end = min(q0 + 64, len);

    for (int j0 = 0; j0 < kv_end; j0 += 64) {
        __syncthreads();   // protect Kt/Vs/Pt reuse from previous iteration
        // load K transposed -> Kt[dim][key], V direct -> Vs[key][dim]
#pragma unroll
        for (int i = 0; i < 4; i++) {
            int idx = tid + i * 256;
            int key = idx >> 4, c4 = (idx & 15) * 4;
            size_t g = ((size_t)(b * NN + j0 + key) * DOUT) + h * HD + c4;
            float4 kv = *(const float4*)(g_K + g);
            Kt[(c4 + 0) * 65 + key] = kv.x;
            Kt[(c4 + 1) * 65 + key] = kv.y;
            Kt[(c4 + 2) * 65 + key] = kv.z;
            Kt[(c4 + 3) * 65 + key] = kv.w;
            *(float4*)(Vs + key * 64 + c4) = *(const float4*)(g_V + g);
        }
        __syncthreads();

        // S = Q @ K^T  (4x4 per thread)
        float acc[16];
#pragma unroll
        for (int i = 0; i < 16; i++) acc[i] = 0.f;
#pragma unroll 8
        for (int kk = 0; kk < 64; kk++) {
            float qa0 = Qs[(ty * 4 + 0) * 64 + kk];
            float qa1 = Qs[(ty * 4 + 1) * 64 + kk];
            float qa2 = Qs[(ty * 4 + 2) * 64 + kk];
            float qa3 = Qs[(ty * 4 + 3) * 64 + kk];
            float kb0 = Kt[kk * 65 + tx * 4 + 0];
            float kb1 = Kt[kk * 65 + tx * 4 + 1];
            float kb2 = Kt[kk * 65 + tx * 4 + 2];
            float kb3 = Kt[kk * 65 + tx * 4 + 3];
            acc[0]  += qa0 * kb0; acc[1]  += qa0 * kb1; acc[2]  += qa0 * kb2; acc[3]  += qa0 * kb3;
            acc[4]  += qa1 * kb0; acc[5]  += qa1 * kb1; acc[6]  += qa1 * kb2; acc[7]  += qa1 * kb3;
            acc[8]  += qa2 * kb0; acc[9]  += qa2 * kb1; acc[10] += qa2 * kb2; acc[11] += qa2 * kb3;
            acc[12] += qa3 * kb0; acc[13] += qa3 * kb1; acc[14] += qa3 * kb2; acc[15] += qa3 * kb3;
        }

        // mask + online softmax per row
#pragma unroll
        for (int i = 0; i < 4; i++) {
            const int q = q0 + ty * 4 + i;
            float rm = -CUDART_INF_F;
#pragma unroll
            for (int j = 0; j < 4; j++) {
                int key = j0 + tx * 4 + j;
                float s = acc[i * 4 + j] * 0.125f;
                if (key > q || key >= len) s = -CUDART_INF_F;
                acc[i * 4 + j] = s;
                rm = fmaxf(rm, s);
            }
            rm = fmaxf(rm, __shfl_xor_sync(0xffffffffu, rm, 1));
            rm = fmaxf(rm, __shfl_xor_sync(0xffffffffu, rm, 2));
            rm = fmaxf(rm, __shfl_xor_sync(0xffffffffu, rm, 4));
            rm = fmaxf(rm, __shfl_xor_sync(0xffffffffu, rm, 8));
            float mnew = fmaxf(m[i], rm);          // finite: key j0 always valid
            float corr = __expf(m[i] - mnew);
            float rs = 0.f;
#pragma unroll
            for (int j = 0; j < 4; j++) {
                float p = __expf(acc[i * 4 + j] - mnew);
                acc[i * 4 + j] = p;
                rs += p;
            }
            rs += __shfl_xor_sync(0xffffffffu, rs, 1);
            rs += __shfl_xor_sync(0xffffffffu, rs, 2);
            rs += __shfl_xor_sync(0xffffffffu, rs, 4);
            rs += __shfl_xor_sync(0xffffffffu, rs, 8);
            l[i] = l[i] * corr + rs;
            m[i] = mnew;
#pragma unroll
            for (int j = 0; j < 4; j++) O[i * 4 + j] *= corr;
        }

        // write P^T tile: Pt[key][row]
#pragma unroll
        for (int j = 0; j < 4; j++) {
            int key = tx * 4 + j;
#pragma unroll
            for (int i = 0; i < 4; i++)
                Pt[key * 65 + ty * 4 + i] = acc[i * 4 + j];
        }
        __syncthreads();

        // O += P @ V  (4 rows x 4 dims per thread)
#pragma unroll 8
        for (int k = 0; k < 64; k++) {
            float p0 = Pt[k * 65 + ty * 4 + 0];
            float p1 = Pt[k * 65 + ty * 4 + 1];
            float p2 = Pt[k * 65 + ty * 4 + 2];
            float p3 = Pt[k * 65 + ty * 4 + 3];
            float4 vv = *(float4*)(Vs + k * 64 + tx * 4);
            O[0]  += p0 * vv.x; O[1]  += p0 * vv.y; O[2]  += p0 * vv.z; O[3]  += p0 * vv.w;
            O[4]  += p1 * vv.x; O[5]  += p1 * vv.y; O[6]  += p1 * vv.z; O[7]  += p1 * vv.w;
            O[8]  += p2 * vv.x; O[9]  += p2 * vv.y; O[10] += p2 * vv.z; O[11] += p2 * vv.w;
            O[12] += p3 * vv.x; O[13] += p3 * vv.y; O[14] += p3 * vv.z; O[15] += p3 * vv.w;
        }
    }

    // epilogue
#pragma unroll
    for (int i = 0; i < 4; i++) {
        float inv = 1.f / l[i];
        float4 v = make_float4(O[i * 4] * inv, O[i * 4 + 1] * inv,
                               O[i * 4 + 2] * inv, O[i * 4 + 3] * inv);
        *(float4*)(g_C + ((size_t)(b * NN + q0 + ty * 4 + i) * DOUT) + h * HD + tx * 4) = v;
    }
}

// ---------------- launch ------------------------------------------------------
extern "C" void kernel_launch(void* const* d_in, const int* in_sizes, int n_in,
                              void* d_out, int out_size) {
    const float* x    = (const float*)d_in[0];
    const int*   mask = (const int*)d_in[1];
    const float* Wq   = (const float*)d_in[2];
    const float* Wk   = (const float*)d_in[3];
    const float* Wv   = (const float*)d_in[4];
    const float* Wo   = (const float*)d_in[5];
    const float* bo   = (const float*)d_in[6];
    float* out = (float*)d_out;

    cudaFuncSetAttribute(attn_tile_kernel,
                         cudaFuncAttributeMaxDynamicSharedMemorySize, ATT_SMEM_BYTES);

    len_kernel<<<BB, 256>>>(mask);

    dim3 gq(DOUT / 128, MTOT / 128, 3);
    qkv_gemm<<<gq, 256>>>(x, Wq, Wk, Wv);

    dim3 ga(NN / 64, NH, BB);
    attn_tile_kernel<<<ga, 256, ATT_SMEM_BYTES>>>();

    dim3 go(DOUT / 128, MTOT / 128, 1);
    out_gemm<<<go, 256>>>(Wo, bo, out);
}

// round 4
// speedup vs baseline: 3.6458x; 1.6256x over previous
#include <cuda_runtime.h>
#include <cuda_bf16.h>
#include <math_constants.h>
#include <cstdint>

// Problem constants
#define BB 4
#define NN 2048
#define DIN 1024
#define DOUT 1024
#define NH 16
#define HD 64
#define MTOT (BB * NN)          // 8192 rows

// ---------------- scratch (device globals; no allocation allowed) -----------
__device__ float g_Q[MTOT * DOUT];
__device__ float g_K[MTOT * DOUT];
__device__ float g_V[MTOT * DOUT];
__device__ float g_C[MTOT * DOUT];
__device__ int   g_len[BB];

// ---------------- per-batch valid length from right-padding mask ------------
__global__ void len_kernel(const int* __restrict__ mask) {
    int b = blockIdx.x;
    int s = 0;
    for (int i = threadIdx.x; i < NN; i += 256) s += mask[b * NN + i];
    __shared__ int sh[256];
    sh[threadIdx.x] = s;
    __syncthreads();
    for (int off = 128; off; off >>= 1) {
        if (threadIdx.x < off) sh[threadIdx.x] += sh[threadIdx.x + off];
        __syncthreads();
    }
    if (threadIdx.x == 0) g_len[b] = sh[0];
}

// ---------------- tf32 tensor-core GEMM (mma.sync m16n8k8) -------------------
__device__ __forceinline__ uint32_t f2tf32(float f) {
    uint32_t u;
    asm("cvt.rna.tf32.f32 %0, %1;" : "=r"(u) : "f"(f));
    return u;
}

__device__ __forceinline__ void mma_tf32(float* d, const uint32_t* a, const uint32_t* b) {
    asm volatile(
        "mma.sync.aligned.m16n8k8.row.col.f32.tf32.tf32.f32 "
        "{%0,%1,%2,%3}, {%4,%5,%6,%7}, {%8,%9}, {%0,%1,%2,%3};"
        : "+f"(d[0]), "+f"(d[1]), "+f"(d[2]), "+f"(d[3])
        : "r"(a[0]), "r"(a[1]), "r"(a[2]), "r"(a[3]), "r"(b[0]), "r"(b[1]));
}

// C = A[M,1024] @ W[1024,1024] (+bias). Tile 128x128x32, 256 thr, 8 warps 2x4.
// As[128][36] (m-major, tf32 bits), Bs[32][136] (k-major).
__device__ __forceinline__ void gemm_body(const float* __restrict__ A,
                                          const float* __restrict__ W,
                                          float* __restrict__ C,
                                          const float* __restrict__ bias,
                                          int bm, int bn) {
    __shared__ uint32_t As[128][36];
    __shared__ uint32_t Bs[32][136];

    const int tid = threadIdx.x;
    const int lane = tid & 31;
    const int wid = tid >> 5;
    const int wm = (wid >> 2) * 64;    // 0 / 64
    const int wn = (wid & 3) * 32;     // 0 / 32 / 64 / 96
    const int r = lane >> 2;           // 0..7
    const int c = lane & 3;            // 0..3

    float acc[4][4][4];
#pragma unroll
    for (int mt = 0; mt < 4; mt++)
#pragma unroll
        for (int nt = 0; nt < 4; nt++)
#pragma unroll
            for (int i = 0; i < 4; i++) acc[mt][nt][i] = 0.f;

    for (int k0 = 0; k0 < 1024; k0 += 32) {
        // stage A tile (128x32) as tf32
#pragma unroll
        for (int i = 0; i < 4; i++) {
            int idx = tid + i * 256;
            int rr = idx >> 3, c4 = (idx & 7) * 4;
            float4 v = *(const float4*)(A + (size_t)(bm + rr) * 1024 + k0 + c4);
            uint4 u = make_uint4(f2tf32(v.x), f2tf32(v.y), f2tf32(v.z), f2tf32(v.w));
            *(uint4*)(&As[rr][c4]) = u;
        }
        // stage B tile (32x128) as tf32
#pragma unroll
        for (int i = 0; i < 4; i++) {
            int idx = tid + i * 256;
            int kr = idx >> 5, n4 = (idx & 31) * 4;
            float4 v = *(const float4*)(W + (size_t)(k0 + kr) * 1024 + bn + n4);
            uint4 u = make_uint4(f2tf32(v.x), f2tf32(v.y), f2tf32(v.z), f2tf32(v.w));
            *(uint4*)(&Bs[kr][n4]) = u;
        }
        __syncthreads();

#pragma unroll
        for (int ks = 0; ks < 32; ks += 8) {
            uint32_t af[4][4];
#pragma unroll
            for (int mt = 0; mt < 4; mt++) {
                int row = wm + mt * 16 + r;
                af[mt][0] = As[row][ks + c];
                af[mt][1] = As[row + 8][ks + c];
                af[mt][2] = As[row][ks + c + 4];
                af[mt][3] = As[row + 8][ks + c + 4];
            }
            uint32_t bf[4][2];
#pragma unroll
            for (int nt = 0; nt < 4; nt++) {
                int col = wn + nt * 8 + r;
                bf[nt][0] = Bs[ks + c][col];
                bf[nt][1] = Bs[ks + c + 4][col];
            }
#pragma unroll
            for (int mt = 0; mt < 4; mt++)
#pragma unroll
                for (int nt = 0; nt < 4; nt++)
                    mma_tf32(acc[mt][nt], af[mt], bf[nt]);
        }
        __syncthreads();
    }

    // epilogue
#pragma unroll
    for (int mt = 0; mt < 4; mt++) {
        int row0 = bm + wm + mt * 16 + r;
        int row1 = row0 + 8;
#pragma unroll
        for (int nt = 0; nt < 4; nt++) {
            int col = bn + wn + nt * 8 + c * 2;
            float b0 = bias ? bias[col] : 0.f;
            float b1 = bias ? bias[col + 1] : 0.f;
            *(float2*)(C + (size_t)row0 * 1024 + col) =
                make_float2(acc[mt][nt][0] + b0, acc[mt][nt][1] + b1);
            *(float2*)(C + (size_t)row1 * 1024 + col) =
                make_float2(acc[mt][nt][2] + b0, acc[mt][nt][3] + b1);
        }
    }
}

__global__ __launch_bounds__(256, 2) void qkv_gemm_tc(const float* __restrict__ A,
                                                      const float* __restrict__ W0,
                                                      const float* __restrict__ W1,
                                                      const float* __restrict__ W2) {
    const float* W = (blockIdx.z == 0) ? W0 : (blockIdx.z == 1) ? W1 : W2;
    float* C = (blockIdx.z == 0) ? g_Q : (blockIdx.z == 1) ? g_K : g_V;
    gemm_body(A, W, C, nullptr, blockIdx.y * 128, blockIdx.x * 128);
}

__global__ __launch_bounds__(256, 2) void out_gemm_tc(const float* __restrict__ Wo,
                                                      const float* __restrict__ bo,
                                                      float* __restrict__ Out) {
    gemm_body(g_C, Wo, Out, bo, blockIdx.y * 128, blockIdx.x * 128);
}

// ---------------- tile-GEMM flash attention (fp32) ---------------------------
#define QS_OFF 0
#define KT_OFF 4096
#define VS_OFF (4096 + 4160)
#define PT_OFF (4096 + 4160 + 4096)
#define ATT_SMEM_FLOATS (4096 + 4160 + 4096 + 4160)
#define ATT_SMEM_BYTES (ATT_SMEM_FLOATS * 4)

__global__ __launch_bounds__(256) void attn_tile_kernel() {
    extern __shared__ float sm[];
    float* Qs = sm + QS_OFF;   // [row][dim]   64x64
    float* Kt = sm + KT_OFF;   // [dim][key]   64x65
    float* Vs = sm + VS_OFF;   // [key][dim]   64x64
    float* Pt = sm + PT_OFF;   // [key][row]   64x65

    const int b = blockIdx.z;
    const int h = blockIdx.y;
    const int q0 = blockIdx.x * 64;
    const int len = g_len[b];
    const int tid = threadIdx.x;
    const int tx = tid & 15;
    const int ty = tid >> 4;

#pragma unroll
    for (int i = 0; i < 4; i++) {
        int idx = tid + i * 256;
        int r = idx >> 4, c4 = (idx & 15) * 4;
        *(float4*)(Qs + r * 64 + c4) =
            *(const float4*)(g_Q + ((size_t)(b * NN + q0 + r) * DOUT) + h * HD + c4);
    }

    float O[16];
#pragma unroll
    for (int i = 0; i < 16; i++) O[i] = 0.f;
    float m[4], l[4];
#pragma unroll
    for (int i = 0; i < 4; i++) { m[i] = -CUDART_INF_F; l[i] = 0.f; }

    const int kv_end = min(q0 + 64, len);

    for (int j0 = 0; j0 < kv_end; j0 += 64) {
        __syncthreads();
#pragma unroll
        for (int i = 0; i < 4; i++) {
            int idx = tid + i * 256;
            int key = idx >> 4, c4 = (idx & 15) * 4;
            size_t g = ((size_t)(b * NN + j0 + key) * DOUT) + h * HD + c4;
            float4 kv = *(const float4*)(g_K + g);
            Kt[(c4 + 0) * 65 + key] = kv.x;
            Kt[(c4 + 1) * 65 + key] = kv.y;
            Kt[(c4 + 2) * 65 + key] = kv.z;
            Kt[(c4 + 3) * 65 + key] = kv.w;
            *(float4*)(Vs + key * 64 + c4) = *(const float4*)(g_V + g);
        }
        __syncthreads();

        float acc[16];
#pragma unroll
        for (int i = 0; i < 16; i++) acc[i] = 0.f;
#pragma unroll 8
        for (int kk = 0; kk < 64; kk++) {
            float qa0 = Qs[(ty * 4 + 0) * 64 + kk];
            float qa1 = Qs[(ty * 4 + 1) * 64 + kk];
            float qa2 = Qs[(ty * 4 + 2) * 64 + kk];
            float qa3 = Qs[(ty * 4 + 3) * 64 + kk];
            float kb0 = Kt[kk * 65 + tx * 4 + 0];
            float kb1 = Kt[kk * 65 + tx * 4 + 1];
            float kb2 = Kt[kk * 65 + tx * 4 + 2];
            float kb3 = Kt[kk * 65 + tx * 4 + 3];
            acc[0]  += qa0 * kb0; acc[1]  += qa0 * kb1; acc[2]  += qa0 * kb2; acc[3]  += qa0 * kb3;
            acc[4]  += qa1 * kb0; acc[5]  += qa1 * kb1; acc[6]  += qa1 * kb2; acc[7]  += qa1 * kb3;
            acc[8]  += qa2 * kb0; acc[9]  += qa2 * kb1; acc[10] += qa2 * kb2; acc[11] += qa2 * kb3;
            acc[12] += qa3 * kb0; acc[13] += qa3 * kb1; acc[14] += qa3 * kb2; acc[15] += qa3 * kb3;
        }

#pragma unroll
        for (int i = 0; i < 4; i++) {
            const int q = q0 + ty * 4 + i;
            float rm = -CUDART_INF_F;
#pragma unroll
            for (int j = 0; j < 4; j++) {
                int key = j0 + tx * 4 + j;
                float s = acc[i * 4 + j] * 0.125f;
                if (key > q || key >= len) s = -CUDART_INF_F;
                acc[i * 4 + j] = s;
                rm = fmaxf(rm, s);
            }
            rm = fmaxf(rm, __shfl_xor_sync(0xffffffffu, rm, 1));
            rm = fmaxf(rm, __shfl_xor_sync(0xffffffffu, rm, 2));
            rm = fmaxf(rm, __shfl_xor_sync(0xffffffffu, rm, 4));
            rm = fmaxf(rm, __shfl_xor_sync(0xffffffffu, rm, 8));
            float mnew = fmaxf(m[i], rm);
            float corr = __expf(m[i] - mnew);
            float rs = 0.f;
#pragma unroll
            for (int j = 0; j < 4; j++) {
                float p = __expf(acc[i * 4 + j] - mnew);
                acc[i * 4 + j] = p;
                rs += p;
            }
            rs += __shfl_xor_sync(0xffffffffu, rs, 1);
            rs += __shfl_xor_sync(0xffffffffu, rs, 2);
            rs += __shfl_xor_sync(0xffffffffu, rs, 4);
            rs += __shfl_xor_sync(0xffffffffu, rs, 8);
            l[i] = l[i] * corr + rs;
            m[i] = mnew;
#pragma unroll
            for (int j = 0; j < 4; j++) O[i * 4 + j] *= corr;
        }

#pragma unroll
        for (int j = 0; j < 4; j++) {
            int key = tx * 4 + j;
#pragma unroll
            for (int i = 0; i < 4; i++)
                Pt[key * 65 + ty * 4 + i] = acc[i * 4 + j];
        }
        __syncthreads();

#pragma unroll 8
        for (int k = 0; k < 64; k++) {
            float p0 = Pt[k * 65 + ty * 4 + 0];
            float p1 = Pt[k * 65 + ty * 4 + 1];
            float p2 = Pt[k * 65 + ty * 4 + 2];
            float p3 = Pt[k * 65 + ty * 4 + 3];
            float4 vv = *(float4*)(Vs + k * 64 + tx * 4);
            O[0]  += p0 * vv.x; O[1]  += p0 * vv.y; O[2]  += p0 * vv.z; O[3]  += p0 * vv.w;
            O[4]  += p1 * vv.x; O[5]  += p1 * vv.y; O[6]  += p1 * vv.z; O[7]  += p1 * vv.w;
            O[8]  += p2 * vv.x; O[9]  += p2 * vv.y; O[10] += p2 * vv.z; O[11] += p2 * vv.w;
            O[12] += p3 * vv.x; O[13] += p3 * vv.y; O[14] += p3 * vv.z; O[15] += p3 * vv.w;
        }
    }

#pragma unroll
    for (int i = 0; i < 4; i++) {
        float inv = 1.f / l[i];
        float4 v = make_float4(O[i * 4] * inv, O[i * 4 + 1] * inv,
                               O[i * 4 + 2] * inv, O[i * 4 + 3] * inv);
        *(float4*)(g_C + ((size_t)(b * NN + q0 + ty * 4 + i) * DOUT) + h * HD + tx * 4) = v;
    }
}

// ---------------- launch ------------------------------------------------------
extern "C" void kernel_launch(void* const* d_in, const int* in_sizes, int n_in,
                              void* d_out, int out_size) {
    const float* x    = (const float*)d_in[0];
    const int*   mask = (const int*)d_in[1];
    const float* Wq   = (const float*)d_in[2];
    const float* Wk   = (const float*)d_in[3];
    const float* Wv   = (const float*)d_in[4];
    const float* Wo   = (const float*)d_in[5];
    const float* bo   = (const float*)d_in[6];
    float* out = (float*)d_out;

    cudaFuncSetAttribute(attn_tile_kernel,
                         cudaFuncAttributeMaxDynamicSharedMemorySize, ATT_SMEM_BYTES);

    len_kernel<<<BB, 256>>>(mask);

    dim3 gq(DOUT / 128, MTOT / 128, 3);
    qkv_gemm_tc<<<gq, 256>>>(x, Wq, Wk, Wv);

    dim3 ga(NN / 64, NH, BB);
    attn_tile_kernel<<<ga, 256, ATT_SMEM_BYTES>>>();

    dim3 go(DOUT / 128, MTOT / 128, 1);
    out_gemm_tc<<<go, 256>>>(Wo, bo, out);
}

// round 5
// speedup vs baseline: 6.6673x; 1.8288x over previous
#include <cuda_runtime.h>
#include <cuda_bf16.h>
#include <math_constants.h>
#include <cstdint>

#define BB 4
#define NN 2048
#define DIN 1024
#define DOUT 1024
#define NH 16
#define HD 64
#define MTOT (BB * NN)

__device__ float g_Q[MTOT * DOUT];
__device__ float g_K[MTOT * DOUT];
__device__ float g_V[MTOT * DOUT];
__device__ float g_C[MTOT * DOUT];
__device__ int   g_len[BB];

// ---------------- per-batch valid length ------------------------------------
__global__ void len_kernel(const int* __restrict__ mask) {
    int b = blockIdx.x;
    int s = 0;
    for (int i = threadIdx.x; i < NN; i += 256) s += mask[b * NN + i];
    __shared__ int sh[256];
    sh[threadIdx.x] = s;
    __syncthreads();
    for (int off = 128; off; off >>= 1) {
        if (threadIdx.x < off) sh[threadIdx.x] += sh[threadIdx.x + off];
        __syncthreads();
    }
    if (threadIdx.x == 0) g_len[b] = sh[0];
}

// ---------------- tf32 helpers ----------------------------------------------
__device__ __forceinline__ uint32_t f2tf32(float f) {
    uint32_t u;
    asm("cvt.rna.tf32.f32 %0, %1;" : "=r"(u) : "f"(f));
    return u;
}
__device__ __forceinline__ void mma_tf32(float* d, const uint32_t* a, const uint32_t* b) {
    asm volatile(
        "mma.sync.aligned.m16n8k8.row.col.f32.tf32.tf32.f32 "
        "{%0,%1,%2,%3}, {%4,%5,%6,%7}, {%8,%9}, {%0,%1,%2,%3};"
        : "+f"(d[0]), "+f"(d[1]), "+f"(d[2]), "+f"(d[3])
        : "r"(a[0]), "r"(a[1]), "r"(a[2]), "r"(a[3]), "r"(b[0]), "r"(b[1]));
}

// ---------------- tf32 projection GEMM (128x128x32 tiles) --------------------
__device__ __forceinline__ void gemm_body(const float* __restrict__ A,
                                          const float* __restrict__ W,
                                          float* __restrict__ C,
                                          const float* __restrict__ bias,
                                          int bm, int bn) {
    __shared__ uint32_t As[128][36];
    __shared__ uint32_t Bs[32][136];

    const int tid = threadIdx.x;
    const int lane = tid & 31;
    const int wid = tid >> 5;
    const int wm = (wid >> 2) * 64;
    const int wn = (wid & 3) * 32;
    const int r = lane >> 2;
    const int c = lane & 3;

    float acc[4][4][4];
#pragma unroll
    for (int mt = 0; mt < 4; mt++)
#pragma unroll
        for (int nt = 0; nt < 4; nt++)
#pragma unroll
            for (int i = 0; i < 4; i++) acc[mt][nt][i] = 0.f;

    for (int k0 = 0; k0 < 1024; k0 += 32) {
#pragma unroll
        for (int i = 0; i < 4; i++) {
            int idx = tid + i * 256;
            int rr = idx >> 3, c4 = (idx & 7) * 4;
            float4 v = *(const float4*)(A + (size_t)(bm + rr) * 1024 + k0 + c4);
            uint4 u = make_uint4(f2tf32(v.x), f2tf32(v.y), f2tf32(v.z), f2tf32(v.w));
            *(uint4*)(&As[rr][c4]) = u;
        }
#pragma unroll
        for (int i = 0; i < 4; i++) {
            int idx = tid + i * 256;
            int kr = idx >> 5, n4 = (idx & 31) * 4;
            float4 v = *(const float4*)(W + (size_t)(k0 + kr) * 1024 + bn + n4);
            uint4 u = make_uint4(f2tf32(v.x), f2tf32(v.y), f2tf32(v.z), f2tf32(v.w));
            *(uint4*)(&Bs[kr][n4]) = u;
        }
        __syncthreads();

#pragma unroll
        for (int ks = 0; ks < 32; ks += 8) {
            uint32_t af[4][4];
#pragma unroll
            for (int mt = 0; mt < 4; mt++) {
                int row = wm + mt * 16 + r;
                af[mt][0] = As[row][ks + c];
                af[mt][1] = As[row + 8][ks + c];
                af[mt][2] = As[row][ks + c + 4];
                af[mt][3] = As[row + 8][ks + c + 4];
            }
            uint32_t bf[4][2];
#pragma unroll
            for (int nt = 0; nt < 4; nt++) {
                int col = wn + nt * 8 + r;
                bf[nt][0] = Bs[ks + c][col];
                bf[nt][1] = Bs[ks + c + 4][col];
            }
#pragma unroll
            for (int mt = 0; mt < 4; mt++)
#pragma unroll
                for (int nt = 0; nt < 4; nt++)
                    mma_tf32(acc[mt][nt], af[mt], bf[nt]);
        }
        __syncthreads();
    }

#pragma unroll
    for (int mt = 0; mt < 4; mt++) {
        int row0 = bm + wm + mt * 16 + r;
        int row1 = row0 + 8;
#pragma unroll
        for (int nt = 0; nt < 4; nt++) {
            int col = bn + wn + nt * 8 + c * 2;
            float b0 = bias ? bias[col] : 0.f;
            float b1 = bias ? bias[col + 1] : 0.f;
            *(float2*)(C + (size_t)row0 * 1024 + col) =
                make_float2(acc[mt][nt][0] + b0, acc[mt][nt][1] + b1);
            *(float2*)(C + (size_t)row1 * 1024 + col) =
                make_float2(acc[mt][nt][2] + b0, acc[mt][nt][3] + b1);
        }
    }
}

__global__ __launch_bounds__(256, 2) void qkv_gemm_tc(const float* __restrict__ A,
                                                      const float* __restrict__ W0,
                                                      const float* __restrict__ W1,
                                                      const float* __restrict__ W2) {
    const float* W = (blockIdx.z == 0) ? W0 : (blockIdx.z == 1) ? W1 : W2;
    float* C = (blockIdx.z == 0) ? g_Q : (blockIdx.z == 1) ? g_K : g_V;
    gemm_body(A, W, C, nullptr, blockIdx.y * 128, blockIdx.x * 128);
}

__global__ __launch_bounds__(256, 2) void out_gemm_tc(const float* __restrict__ Wo,
                                                      const float* __restrict__ bo,
                                                      float* __restrict__ Out) {
    gemm_body(g_C, Wo, Out, bo, blockIdx.y * 128, blockIdx.x * 128);
}

// ---------------- tensor-core flash attention --------------------------------
// BQ=128, BK=64. 8 warps; warp w owns query rows [w*16, w*16+16) and ALL keys.
// smem (uint32 tf32 bits): Qs[128][68], Ks[64][68], Vs[64][72], Ps[128][68].
#define AQS 0
#define AKS 8704
#define AVS 13056
#define APS 17664
#define ATT_SMEM_U32 26368
#define ATT_SMEM_BYTES (ATT_SMEM_U32 * 4)

__global__ __launch_bounds__(256) void attn_tc_kernel() {
    extern __shared__ uint32_t sm[];
    uint32_t* Qs = sm + AQS;   // [row][k] stride 68
    uint32_t* Ks = sm + AKS;   // [key][k] stride 68
    uint32_t* Vs = sm + AVS;   // [key][n] stride 72
    uint32_t* Ps = sm + APS;   // [row][k] stride 68 (warp-private rows)

    const int b = blockIdx.z;
    const int h = blockIdx.y;
    const int q0 = blockIdx.x * 128;
    const int len = g_len[b];
    const int tid = threadIdx.x;
    const int lane = tid & 31;
    const int wid = tid >> 5;
    const int wm = wid * 16;          // warp's query-row base within tile
    const int r = lane >> 2;          // 0..7
    const int c = lane & 3;           // 0..3

    // stage Q tile (128x64) as tf32
#pragma unroll
    for (int i = 0; i < 8; i++) {
        int idx = tid + i * 256;
        int rr = idx >> 4, c4 = (idx & 15) * 4;
        float4 v = *(const float4*)(g_Q + ((size_t)(b * NN + q0 + rr) * DOUT) + h * HD + c4);
        uint4 u = make_uint4(f2tf32(v.x), f2tf32(v.y), f2tf32(v.z), f2tf32(v.w));
        *(uint4*)(Qs + rr * 68 + c4) = u;
    }

    float oacc[8][4];
#pragma unroll
    for (int nd = 0; nd < 8; nd++)
#pragma unroll
        for (int i = 0; i < 4; i++) oacc[nd][i] = 0.f;
    float m0 = -CUDART_INF_F, m1 = -CUDART_INF_F;
    float l0 = 0.f, l1 = 0.f;

    const int qrow0 = q0 + wm + r;     // this thread's two query rows
    const int qrow1 = qrow0 + 8;
    const int kv_end = min(q0 + 128, len);

    for (int j0 = 0; j0 < kv_end; j0 += 64) {
        __syncthreads();
        // stage K,V tiles (64x64) as tf32
#pragma unroll
        for (int i = 0; i < 4; i++) {
            int idx = tid + i * 256;
            int key = idx >> 4, c4 = (idx & 15) * 4;
            size_t g = ((size_t)(b * NN + j0 + key) * DOUT) + h * HD + c4;
            float4 kv = *(const float4*)(g_K + g);
            float4 vv = *(const float4*)(g_V + g);
            *(uint4*)(Ks + key * 68 + c4) =
                make_uint4(f2tf32(kv.x), f2tf32(kv.y), f2tf32(kv.z), f2tf32(kv.w));
            *(uint4*)(Vs + key * 72 + c4) =
                make_uint4(f2tf32(vv.x), f2tf32(vv.y), f2tf32(vv.z), f2tf32(vv.w));
        }
        __syncthreads();

        // ---- S = Q @ K^T : warp computes 16x64 ----
        float sacc[8][4];
#pragma unroll
        for (int nt = 0; nt < 8; nt++)
#pragma unroll
            for (int i = 0; i < 4; i++) sacc[nt][i] = 0.f;
#pragma unroll
        for (int ks = 0; ks < 64; ks += 8) {
            uint32_t af[4];
            af[0] = Qs[(wm + r) * 68 + ks + c];
            af[1] = Qs[(wm + r + 8) * 68 + ks + c];
            af[2] = Qs[(wm + r) * 68 + ks + c + 4];
            af[3] = Qs[(wm + r + 8) * 68 + ks + c + 4];
#pragma unroll
            for (int nt = 0; nt < 8; nt++) {
                uint32_t bf[2];
                bf[0] = Ks[(nt * 8 + r) * 68 + ks + c];
                bf[1] = Ks[(nt * 8 + r) * 68 + ks + c + 4];
                mma_tf32(sacc[nt], af, bf);
            }
        }

        // ---- scale + mask + row max ----
        float mx0 = -CUDART_INF_F, mx1 = -CUDART_INF_F;
#pragma unroll
        for (int nt = 0; nt < 8; nt++) {
            int k0i = j0 + nt * 8 + 2 * c;
            int k1i = k0i + 1;
            float s0 = sacc[nt][0] * 0.125f;
            float s1 = sacc[nt][1] * 0.125f;
            float s2 = sacc[nt][2] * 0.125f;
            float s3 = sacc[nt][3] * 0.125f;
            if (k0i > qrow0 || k0i >= len) s0 = -CUDART_INF_F;
            if (k1i > qrow0 || k1i >= len) s1 = -CUDART_INF_F;
            if (k0i > qrow1 || k0i >= len) s2 = -CUDART_INF_F;
            if (k1i > qrow1 || k1i >= len) s3 = -CUDART_INF_F;
            sacc[nt][0] = s0; sacc[nt][1] = s1; sacc[nt][2] = s2; sacc[nt][3] = s3;
            mx0 = fmaxf(mx0, fmaxf(s0, s1));
            mx1 = fmaxf(mx1, fmaxf(s2, s3));
        }
        mx0 = fmaxf(mx0, __shfl_xor_sync(0xffffffffu, mx0, 1));
        mx0 = fmaxf(mx0, __shfl_xor_sync(0xffffffffu, mx0, 2));
        mx1 = fmaxf(mx1, __shfl_xor_sync(0xffffffffu, mx1, 1));
        mx1 = fmaxf(mx1, __shfl_xor_sync(0xffffffffu, mx1, 2));

        float mn0 = fmaxf(m0, mx0);
        float mn1 = fmaxf(m1, mx1);
        float corr0 = __expf(m0 - mn0);
        float corr1 = __expf(m1 - mn1);

        // ---- exp + row sum + write P (tf32) ----
        float sum0 = 0.f, sum1 = 0.f;
#pragma unroll
        for (int nt = 0; nt < 8; nt++) {
            float p0 = __expf(sacc[nt][0] - mn0);
            float p1 = __expf(sacc[nt][1] - mn0);
            float p2 = __expf(sacc[nt][2] - mn1);
            float p3 = __expf(sacc[nt][3] - mn1);
            sum0 += p0 + p1;
            sum1 += p2 + p3;
            *(uint2*)(Ps + (wm + r) * 68 + nt * 8 + 2 * c) =
                make_uint2(f2tf32(p0), f2tf32(p1));
            *(uint2*)(Ps + (wm + r + 8) * 68 + nt * 8 + 2 * c) =
                make_uint2(f2tf32(p2), f2tf32(p3));
        }
        sum0 += __shfl_xor_sync(0xffffffffu, sum0, 1);
        sum0 += __shfl_xor_sync(0xffffffffu, sum0, 2);
        sum1 += __shfl_xor_sync(0xffffffffu, sum1, 1);
        sum1 += __shfl_xor_sync(0xffffffffu, sum1, 2);
        l0 = l0 * corr0 + sum0;
        l1 = l1 * corr1 + sum1;
        m0 = mn0;
        m1 = mn1;
#pragma unroll
        for (int nd = 0; nd < 8; nd++) {
            oacc[nd][0] *= corr0; oacc[nd][1] *= corr0;
            oacc[nd][2] *= corr1; oacc[nd][3] *= corr1;
        }
        __syncwarp();

        // ---- O += P @ V : warp computes 16x64 ----
#pragma unroll
        for (int ks = 0; ks < 64; ks += 8) {
            uint32_t af[4];
            af[0] = Ps[(wm + r) * 68 + ks + c];
            af[1] = Ps[(wm + r + 8) * 68 + ks + c];
            af[2] = Ps[(wm + r) * 68 + ks + c + 4];
            af[3] = Ps[(wm + r + 8) * 68 + ks + c + 4];
#pragma unroll
            for (int nd = 0; nd < 8; nd++) {
                uint32_t bf[2];
                bf[0] = Vs[(ks + c) * 72 + nd * 8 + r];
                bf[1] = Vs[(ks + c + 4) * 72 + nd * 8 + r];
                mma_tf32(oacc[nd], af, bf);
            }
        }
    }

    // ---- epilogue ----
    float inv0 = 1.f / l0;
    float inv1 = 1.f / l1;
    float* out0 = g_C + ((size_t)(b * NN + qrow0) * DOUT) + h * HD;
    float* out1 = g_C + ((size_t)(b * NN + qrow1) * DOUT) + h * HD;
#pragma unroll
    for (int nd = 0; nd < 8; nd++) {
        int col = nd * 8 + 2 * c;
        *(float2*)(out0 + col) = make_float2(oacc[nd][0] * inv0, oacc[nd][1] * inv0);
        *(float2*)(out1 + col) = make_float2(oacc[nd][2] * inv1, oacc[nd][3] * inv1);
    }
}

// ---------------- launch ------------------------------------------------------
extern "C" void kernel_launch(void* const* d_in, const int* in_sizes, int n_in,
                              void* d_out, int out_size) {
    const float* x    = (const float*)d_in[0];
    const int*   mask = (const int*)d_in[1];
    const float* Wq   = (const float*)d_in[2];
    const float* Wk   = (const float*)d_in[3];
    const float* Wv   = (const float*)d_in[4];
    const float* Wo   = (const float*)d_in[5];
    const float* bo   = (const float*)d_in[6];
    float* out = (float*)d_out;

    cudaFuncSetAttribute(attn_tc_kernel,
                         cudaFuncAttributeMaxDynamicSharedMemorySize, ATT_SMEM_BYTES);

    len_kernel<<<BB, 256>>>(mask);

    dim3 gq(DOUT / 128, MTOT / 128, 3);
    qkv_gemm_tc<<<gq, 256>>>(x, Wq, Wk, Wv);

    dim3 ga(NN / 128, NH, BB);
    attn_tc_kernel<<<ga, 256, ATT_SMEM_BYTES>>>();

    dim3 go(DOUT / 128, MTOT / 128, 1);
    out_gemm_tc<<<go, 256>>>(Wo, bo, out);
}

// round 6
// speedup vs baseline: 6.9461x; 1.0418x over previous
#include <cuda_runtime.h>
#include <cuda_bf16.h>
#include <math_constants.h>
#include <cstdint>

#define BB 4
#define NN 2048
#define DIN 1024
#define DOUT 1024
#define NH 16
#define HD 64
#define MTOT (BB * NN)

__device__ float g_Q[MTOT * DOUT];
__device__ float g_K[MTOT * DOUT];
__device__ float g_V[MTOT * DOUT];
__device__ float g_C[MTOT * DOUT];
__device__ int   g_len[BB];

// ---------------- per-batch valid length ------------------------------------
__global__ void len_kernel(const int* __restrict__ mask) {
    int b = blockIdx.x;
    int s = 0;
    for (int i = threadIdx.x; i < NN; i += 256) s += mask[b * NN + i];
    __shared__ int sh[256];
    sh[threadIdx.x] = s;
    __syncthreads();
    for (int off = 128; off; off >>= 1) {
        if (threadIdx.x < off) sh[threadIdx.x] += sh[threadIdx.x + off];
        __syncthreads();
    }
    if (threadIdx.x == 0) g_len[b] = sh[0];
}

// ---------------- tf32 / cp.async helpers ------------------------------------
__device__ __forceinline__ uint32_t f2tf32(float f) {
    uint32_t u;
    asm("cvt.rna.tf32.f32 %0, %1;" : "=r"(u) : "f"(f));
    return u;
}
__device__ __forceinline__ void mma_tf32(float* d, const uint32_t* a, const uint32_t* b) {
    asm volatile(
        "mma.sync.aligned.m16n8k8.row.col.f32.tf32.tf32.f32 "
        "{%0,%1,%2,%3}, {%4,%5,%6,%7}, {%8,%9}, {%0,%1,%2,%3};"
        : "+f"(d[0]), "+f"(d[1]), "+f"(d[2]), "+f"(d[3])
        : "r"(a[0]), "r"(a[1]), "r"(a[2]), "r"(a[3]), "r"(b[0]), "r"(b[1]));
}
__device__ __forceinline__ void cp16(void* s, const void* g) {
    uint32_t sa = (uint32_t)__cvta_generic_to_shared(s);
    asm volatile("cp.async.ca.shared.global [%0], [%1], 16;" :: "r"(sa), "l"(g));
}
#define CP_COMMIT() asm volatile("cp.async.commit_group;" ::: "memory")
#define CP_WAIT0()  asm volatile("cp.async.wait_group 0;" ::: "memory")

// ---------------- tf32 projection GEMM, cp.async double-buffered -------------
// Tile 128x128x32, 8 warps 2x4, raw f32 staged; cvt to tf32 at fragment load.
// Stage layout (floats): Af[128][36] then Bf[32][136]; GSTAGE floats per stage.
#define GSTAGE (128 * 36 + 32 * 136)          // 8960 floats
#define GEMM_SMEM_BYTES (2 * GSTAGE * 4)      // 71680 B

__device__ __forceinline__ void gemm_body(const float* __restrict__ A,
                                          const float* __restrict__ W,
                                          float* __restrict__ C,
                                          const float* __restrict__ bias,
                                          int bm, int bn, float* dsm) {
    const int tid = threadIdx.x;
    const int lane = tid & 31;
    const int wid = tid >> 5;
    const int wm = (wid >> 2) * 64;
    const int wn = (wid & 3) * 32;
    const int r = lane >> 2;
    const int c = lane & 3;

    float acc[4][4][4];
#pragma unroll
    for (int mt = 0; mt < 4; mt++)
#pragma unroll
        for (int nt = 0; nt < 4; nt++)
#pragma unroll
            for (int i = 0; i < 4; i++) acc[mt][nt][i] = 0.f;

    // per-thread staging coordinates
    const int arr = tid >> 3, ac4 = (tid & 7) * 4;      // A: 128 rows x 32 cols, 2 iters
    const int bkr = tid >> 5, bn4 = (tid & 31) * 4;     // B: 32 rows x 128 cols, 4 iters

    auto load_stage = [&](int s, int k0) {
        float* Af = dsm + s * GSTAGE;
        float* Bf = Af + 128 * 36;
#pragma unroll
        for (int i = 0; i < 4; i++) {
            int rr = arr + i * 32;
            cp16(Af + rr * 36 + ac4, A + (size_t)(bm + rr) * 1024 + k0 + ac4);
        }
#pragma unroll
        for (int i = 0; i < 4; i++) {
            int kr = bkr + i * 8;
            cp16(Bf + kr * 136 + bn4, W + (size_t)(k0 + kr) * 1024 + bn + bn4);
        }
    };

    load_stage(0, 0);
    CP_COMMIT();

    for (int kt = 0; kt < 32; kt++) {
        CP_WAIT0();
        __syncthreads();
        if (kt + 1 < 32) {
            load_stage((kt + 1) & 1, (kt + 1) * 32);
            CP_COMMIT();
        }
        const float* Af = dsm + (kt & 1) * GSTAGE;
        const float* Bf = Af + 128 * 36;

#pragma unroll
        for (int ks = 0; ks < 32; ks += 8) {
            uint32_t af[4][4];
#pragma unroll
            for (int mt = 0; mt < 4; mt++) {
                int row = wm + mt * 16 + r;
                af[mt][0] = f2tf32(Af[row * 36 + ks + c]);
                af[mt][1] = f2tf32(Af[(row + 8) * 36 + ks + c]);
                af[mt][2] = f2tf32(Af[row * 36 + ks + c + 4]);
                af[mt][3] = f2tf32(Af[(row + 8) * 36 + ks + c + 4]);
            }
            uint32_t bf[4][2];
#pragma unroll
            for (int nt = 0; nt < 4; nt++) {
                int col = wn + nt * 8 + r;
                bf[nt][0] = f2tf32(Bf[(ks + c) * 136 + col]);
                bf[nt][1] = f2tf32(Bf[(ks + c + 4) * 136 + col]);
            }
#pragma unroll
            for (int mt = 0; mt < 4; mt++)
#pragma unroll
                for (int nt = 0; nt < 4; nt++)
                    mma_tf32(acc[mt][nt], af[mt], bf[nt]);
        }
        __syncthreads();
    }

    // epilogue
#pragma unroll
    for (int mt = 0; mt < 4; mt++) {
        int row0 = bm + wm + mt * 16 + r;
        int row1 = row0 + 8;
#pragma unroll
        for (int nt = 0; nt < 4; nt++) {
            int col = bn + wn + nt * 8 + c * 2;
            float b0 = bias ? bias[col] : 0.f;
            float b1 = bias ? bias[col + 1] : 0.f;
            *(float2*)(C + (size_t)row0 * 1024 + col) =
                make_float2(acc[mt][nt][0] + b0, acc[mt][nt][1] + b1);
            *(float2*)(C + (size_t)row1 * 1024 + col) =
                make_float2(acc[mt][nt][2] + b0, acc[mt][nt][3] + b1);
        }
    }
}

__global__ __launch_bounds__(256, 2) void qkv_gemm_tc(const float* __restrict__ A,
                                                      const float* __restrict__ W0,
                                                      const float* __restrict__ W1,
                                                      const float* __restrict__ W2) {
    extern __shared__ float dsm[];
    const float* W = (blockIdx.z == 0) ? W0 : (blockIdx.z == 1) ? W1 : W2;
    float* C = (blockIdx.z == 0) ? g_Q : (blockIdx.z == 1) ? g_K : g_V;
    gemm_body(A, W, C, nullptr, blockIdx.y * 128, blockIdx.x * 128, dsm);
}

__global__ __launch_bounds__(256, 2) void out_gemm_tc(const float* __restrict__ Wo,
                                                      const float* __restrict__ bo,
                                                      float* __restrict__ Out) {
    extern __shared__ float dsm[];
    gemm_body(g_C, Wo, Out, bo, blockIdx.y * 128, blockIdx.x * 128, dsm);
}

// ---------------- tensor-core flash attention (unchanged from R5) ------------
#define AQS 0
#define AKS 8704
#define AVS 13056
#define APS 17664
#define ATT_SMEM_U32 26368
#define ATT_SMEM_BYTES (ATT_SMEM_U32 * 4)

__global__ __launch_bounds__(256) void attn_tc_kernel() {
    extern __shared__ uint32_t sm[];
    uint32_t* Qs = sm + AQS;   // [row][k] stride 68
    uint32_t* Ks = sm + AKS;   // [key][k] stride 68
    uint32_t* Vs = sm + AVS;   // [key][n] stride 72
    uint32_t* Ps = sm + APS;   // [row][k] stride 68 (warp-private rows)

    const int b = blockIdx.z;
    const int h = blockIdx.y;
    const int q0 = blockIdx.x * 128;
    const int len = g_len[b];
    const int tid = threadIdx.x;
    const int lane = tid & 31;
    const int wid = tid >> 5;
    const int wm = wid * 16;
    const int r = lane >> 2;
    const int c = lane & 3;

#pragma unroll
    for (int i = 0; i < 8; i++) {
        int idx = tid + i * 256;
        int rr = idx >> 4, c4 = (idx & 15) * 4;
        float4 v = *(const float4*)(g_Q + ((size_t)(b * NN + q0 + rr) * DOUT) + h * HD + c4);
        uint4 u = make_uint4(f2tf32(v.x), f2tf32(v.y), f2tf32(v.z), f2tf32(v.w));
        *(uint4*)(Qs + rr * 68 + c4) = u;
    }

    float oacc[8][4];
#pragma unroll
    for (int nd = 0; nd < 8; nd++)
#pragma unroll
        for (int i = 0; i < 4; i++) oacc[nd][i] = 0.f;
    float m0 = -CUDART_INF_F, m1 = -CUDART_INF_F;
    float l0 = 0.f, l1 = 0.f;

    const int qrow0 = q0 + wm + r;
    const int qrow1 = qrow0 + 8;
    const int kv_end = min(q0 + 128, len);

    for (int j0 = 0; j0 < kv_end; j0 += 64) {
        __syncthreads();
#pragma unroll
        for (int i = 0; i < 4; i++) {
            int idx = tid + i * 256;
            int key = idx >> 4, c4 = (idx & 15) * 4;
            size_t g = ((size_t)(b * NN + j0 + key) * DOUT) + h * HD + c4;
            float4 kv = *(const float4*)(g_K + g);
            float4 vv = *(const float4*)(g_V + g);
            *(uint4*)(Ks + key * 68 + c4) =
                make_uint4(f2tf32(kv.x), f2tf32(kv.y), f2tf32(kv.z), f2tf32(kv.w));
            *(uint4*)(Vs + key * 72 + c4) =
                make_uint4(f2tf32(vv.x), f2tf32(vv.y), f2tf32(vv.z), f2tf32(vv.w));
        }
        __syncthreads();

        float sacc[8][4];
#pragma unroll
        for (int nt = 0; nt < 8; nt++)
#pragma unroll
            for (int i = 0; i < 4; i++) sacc[nt][i] = 0.f;
#pragma unroll
        for (int ks = 0; ks < 64; ks += 8) {
            uint32_t af[4];
            af[0] = Qs[(wm + r) * 68 + ks + c];
            af[1] = Qs[(wm + r + 8) * 68 + ks + c];
            af[2] = Qs[(wm + r) * 68 + ks + c + 4];
            af[3] = Qs[(wm + r + 8) * 68 + ks + c + 4];
#pragma unroll
            for (int nt = 0; nt < 8; nt++) {
                uint32_t bf[2];
                bf[0] = Ks[(nt * 8 + r) * 68 + ks + c];
                bf[1] = Ks[(nt * 8 + r) * 68 + ks + c + 4];
                mma_tf32(sacc[nt], af, bf);
            }
        }

        float mx0 = -CUDART_INF_F, mx1 = -CUDART_INF_F;
#pragma unroll
        for (int nt = 0; nt < 8; nt++) {
            int k0i = j0 + nt * 8 + 2 * c;
            int k1i = k0i + 1;
            float s0 = sacc[nt][0] * 0.125f;
            float s1 = sacc[nt][1] * 0.125f;
            float s2 = sacc[nt][2] * 0.125f;
            float s3 = sacc[nt][3] * 0.125f;
            if (k0i > qrow0 || k0i >= len) s0 = -CUDART_INF_F;
            if (k1i > qrow0 || k1i >= len) s1 = -CUDART_INF_F;
            if (k0i > qrow1 || k0i >= len) s2 = -CUDART_INF_F;
            if (k1i > qrow1 || k1i >= len) s3 = -CUDART_INF_F;
            sacc[nt][0] = s0; sacc[nt][1] = s1; sacc[nt][2] = s2; sacc[nt][3] = s3;
            mx0 = fmaxf(mx0, fmaxf(s0, s1));
            mx1 = fmaxf(mx1, fmaxf(s2, s3));
        }
        mx0 = fmaxf(mx0, __shfl_xor_sync(0xffffffffu, mx0, 1));
        mx0 = fmaxf(mx0, __shfl_xor_sync(0xffffffffu, mx0, 2));
        mx1 = fmaxf(mx1, __shfl_xor_sync(0xffffffffu, mx1, 1));
        mx1 = fmaxf(mx1, __shfl_xor_sync(0xffffffffu, mx1, 2));

        float mn0 = fmaxf(m0, mx0);
        float mn1 = fmaxf(m1, mx1);
        float corr0 = __expf(m0 - mn0);
        float corr1 = __expf(m1 - mn1);

        float sum0 = 0.f, sum1 = 0.f;
#pragma unroll
        for (int nt = 0; nt < 8; nt++) {
            float p0 = __expf(sacc[nt][0] - mn0);
            float p1 = __expf(sacc[nt][1] - mn0);
            float p2 = __expf(sacc[nt][2] - mn1);
            float p3 = __expf(sacc[nt][3] - mn1);
            sum0 += p0 + p1;
            sum1 += p2 + p3;
            *(uint2*)(Ps + (wm + r) * 68 + nt * 8 + 2 * c) =
                make_uint2(f2tf32(p0), f2tf32(p1));
            *(uint2*)(Ps + (wm + r + 8) * 68 + nt * 8 + 2 * c) =
                make_uint2(f2tf32(p2), f2tf32(p3));
        }
        sum0 += __shfl_xor_sync(0xffffffffu, sum0, 1);
        sum0 += __shfl_xor_sync(0xffffffffu, sum0, 2);
        sum1 += __shfl_xor_sync(0xffffffffu, sum1, 1);
        sum1 += __shfl_xor_sync(0xffffffffu, sum1, 2);
        l0 = l0 * corr0 + sum0;
        l1 = l1 * corr1 + sum1;
        m0 = mn0;
        m1 = mn1;
#pragma unroll
        for (int nd = 0; nd < 8; nd++) {
            oacc[nd][0] *= corr0; oacc[nd][1] *= corr0;
            oacc[nd][2] *= corr1; oacc[nd][3] *= corr1;
        }
        __syncwarp();

#pragma unroll
        for (int ks = 0; ks < 64; ks += 8) {
            uint32_t af[4];
            af[0] = Ps[(wm + r) * 68 + ks + c];
            af[1] = Ps[(wm + r + 8) * 68 + ks + c];
            af[2] = Ps[(wm + r) * 68 + ks + c + 4];
            af[3] = Ps[(wm + r + 8) * 68 + ks + c + 4];
#pragma unroll
            for (int nd = 0; nd < 8; nd++) {
                uint32_t bf[2];
                bf[0] = Vs[(ks + c) * 72 + nd * 8 + r];
                bf[1] = Vs[(ks + c + 4) * 72 + nd * 8 + r];
                mma_tf32(oacc[nd], af, bf);
            }
        }
    }

    float inv0 = 1.f / l0;
    float inv1 = 1.f / l1;
    float* out0 = g_C + ((size_t)(b * NN + qrow0) * DOUT) + h * HD;
    float* out1 = g_C + ((size_t)(b * NN + qrow1) * DOUT) + h * HD;
#pragma unroll
    for (int nd = 0; nd < 8; nd++) {
        int col = nd * 8 + 2 * c;
        *(float2*)(out0 + col) = make_float2(oacc[nd][0] * inv0, oacc[nd][1] * inv0);
        *(float2*)(out1 + col) = make_float2(oacc[nd][2] * inv1, oacc[nd][3] * inv1);
    }
}

// ---------------- launch ------------------------------------------------------
extern "C" void kernel_launch(void* const* d_in, const int* in_sizes, int n_in,
                              void* d_out, int out_size) {
    const float* x    = (const float*)d_in[0];
    const int*   mask = (const int*)d_in[1];
    const float* Wq   = (const float*)d_in[2];
    const float* Wk   = (const float*)d_in[3];
    const float* Wv   = (const float*)d_in[4];
    const float* Wo   = (const float*)d_in[5];
    const float* bo   = (const float*)d_in[6];
    float* out = (float*)d_out;

    cudaFuncSetAttribute(attn_tc_kernel,
                         cudaFuncAttributeMaxDynamicSharedMemorySize, ATT_SMEM_BYTES);
    cudaFuncSetAttribute(qkv_gemm_tc,
                         cudaFuncAttributeMaxDynamicSharedMemorySize, GEMM_SMEM_BYTES);
    cudaFuncSetAttribute(out_gemm_tc,
                         cudaFuncAttributeMaxDynamicSharedMemorySize, GEMM_SMEM_BYTES);

    len_kernel<<<BB, 256>>>(mask);

    dim3 gq(DOUT / 128, MTOT / 128, 3);
    qkv_gemm_tc<<<gq, 256, GEMM_SMEM_BYTES>>>(x, Wq, Wk, Wv);

    dim3 ga(NN / 128, NH, BB);
    attn_tc_kernel<<<ga, 256, ATT_SMEM_BYTES>>>();

    dim3 go(DOUT / 128, MTOT / 128, 1);
    out_gemm_tc<<<go, 256, GEMM_SMEM_BYTES>>>(Wo, bo, out);
}

// round 7
// speedup vs baseline: 7.3664x; 1.0605x over previous
#include <cuda_runtime.h>
#include <cuda_bf16.h>
#include <math_constants.h>
#include <cstdint>

#define BB 4
#define NN 2048
#define DIN 1024
#define DOUT 1024
#define NH 16
#define HD 64
#define MTOT (BB * NN)

__device__ float g_Q[MTOT * DOUT];
__device__ float g_K[MTOT * DOUT];
__device__ float g_V[MTOT * DOUT];
__device__ float g_C[MTOT * DOUT];
__device__ int   g_len[BB];

// ---------------- per-batch valid length ------------------------------------
__global__ void len_kernel(const int* __restrict__ mask) {
    int b = blockIdx.x;
    int s = 0;
    for (int i = threadIdx.x; i < NN; i += 256) s += mask[b * NN + i];
    __shared__ int sh[256];
    sh[threadIdx.x] = s;
    __syncthreads();
    for (int off = 128; off; off >>= 1) {
        if (threadIdx.x < off) sh[threadIdx.x] += sh[threadIdx.x + off];
        __syncthreads();
    }
    if (threadIdx.x == 0) g_len[b] = sh[0];
}

// ---------------- tf32 / cp.async helpers ------------------------------------
__device__ __forceinline__ uint32_t f2tf32(float f) {
    uint32_t u;
    asm("cvt.rna.tf32.f32 %0, %1;" : "=r"(u) : "f"(f));
    return u;
}
__device__ __forceinline__ void mma_tf32(float* d, const uint32_t* a, const uint32_t* b) {
    asm volatile(
        "mma.sync.aligned.m16n8k8.row.col.f32.tf32.tf32.f32 "
        "{%0,%1,%2,%3}, {%4,%5,%6,%7}, {%8,%9}, {%0,%1,%2,%3};"
        : "+f"(d[0]), "+f"(d[1]), "+f"(d[2]), "+f"(d[3])
        : "r"(a[0]), "r"(a[1]), "r"(a[2]), "r"(a[3]), "r"(b[0]), "r"(b[1]));
}
__device__ __forceinline__ void cp16(void* s, const void* g) {
    uint32_t sa = (uint32_t)__cvta_generic_to_shared(s);
    asm volatile("cp.async.ca.shared.global [%0], [%1], 16;" :: "r"(sa), "l"(g));
}
#define CP_COMMIT() asm volatile("cp.async.commit_group;" ::: "memory")
#define CP_WAIT0()  asm volatile("cp.async.wait_group 0;" ::: "memory")

// ---------------- tf32 projection GEMM: 128 thr, 4 warps, 64x64 warp tiles ---
// Tile 128x128x32, raw f32 double-buffered via cp.async, cvt at fragment load.
#define GSTAGE (128 * 36 + 32 * 136)          // 8960 floats per stage
#define GEMM_SMEM_BYTES (2 * GSTAGE * 4)      // 71680 B

__device__ __forceinline__ void gemm_body(const float* __restrict__ A,
                                          const float* __restrict__ W,
                                          float* __restrict__ C,
                                          const float* __restrict__ bias,
                                          int bm, int bn, float* dsm) {
    const int tid = threadIdx.x;
    const int lane = tid & 31;
    const int wid = tid >> 5;
    const int wm = (wid >> 1) * 64;    // 0 / 64
    const int wn = (wid & 1) * 64;     // 0 / 64
    const int r = lane >> 2;           // 0..7
    const int c = lane & 3;            // 0..3

    float acc[4][8][4];
#pragma unroll
    for (int mt = 0; mt < 4; mt++)
#pragma unroll
        for (int nt = 0; nt < 8; nt++)
#pragma unroll
            for (int i = 0; i < 4; i++) acc[mt][nt][i] = 0.f;

    // staging coords (128 threads)
    const int arr = tid >> 3, ac4 = (tid & 7) * 4;      // A: 8 iters of 16 rows
    const int bkr = tid >> 5, bn4 = (tid & 31) * 4;     // B: 8 iters of 4 k-rows

    auto load_stage = [&](int s, int k0) {
        float* Af = dsm + s * GSTAGE;
        float* Bf = Af + 128 * 36;
#pragma unroll
        for (int i = 0; i < 8; i++) {
            int rr = arr + i * 16;
            cp16(Af + rr * 36 + ac4, A + (size_t)(bm + rr) * 1024 + k0 + ac4);
        }
#pragma unroll
        for (int i = 0; i < 8; i++) {
            int kr = bkr + i * 4;
            cp16(Bf + kr * 136 + bn4, W + (size_t)(k0 + kr) * 1024 + bn + bn4);
        }
    };

    load_stage(0, 0);
    CP_COMMIT();

    for (int kt = 0; kt < 32; kt++) {
        CP_WAIT0();
        __syncthreads();
        if (kt + 1 < 32) {
            load_stage((kt + 1) & 1, (kt + 1) * 32);
            CP_COMMIT();
        }
        const float* Af = dsm + (kt & 1) * GSTAGE;
        const float* Bf = Af + 128 * 36;

#pragma unroll
        for (int ks = 0; ks < 32; ks += 8) {
            uint32_t af[4][4];
#pragma unroll
            for (int mt = 0; mt < 4; mt++) {
                int row = wm + mt * 16 + r;
                af[mt][0] = f2tf32(Af[row * 36 + ks + c]);
                af[mt][1] = f2tf32(Af[(row + 8) * 36 + ks + c]);
                af[mt][2] = f2tf32(Af[row * 36 + ks + c + 4]);
                af[mt][3] = f2tf32(Af[(row + 8) * 36 + ks + c + 4]);
            }
            uint32_t bf[8][2];
#pragma unroll
            for (int nt = 0; nt < 8; nt++) {
                int col = wn + nt * 8 + r;
                bf[nt][0] = f2tf32(Bf[(ks + c) * 136 + col]);
                bf[nt][1] = f2tf32(Bf[(ks + c + 4) * 136 + col]);
            }
#pragma unroll
            for (int mt = 0; mt < 4; mt++)
#pragma unroll
                for (int nt = 0; nt < 8; nt++)
                    mma_tf32(acc[mt][nt], af[mt], bf[nt]);
        }
        __syncthreads();
    }

    // epilogue
#pragma unroll
    for (int mt = 0; mt < 4; mt++) {
        int row0 = bm + wm + mt * 16 + r;
        int row1 = row0 + 8;
#pragma unroll
        for (int nt = 0; nt < 8; nt++) {
            int col = bn + wn + nt * 8 + c * 2;
            float b0 = bias ? bias[col] : 0.f;
            float b1 = bias ? bias[col + 1] : 0.f;
            *(float2*)(C + (size_t)row0 * 1024 + col) =
                make_float2(acc[mt][nt][0] + b0, acc[mt][nt][1] + b1);
            *(float2*)(C + (size_t)row1 * 1024 + col) =
                make_float2(acc[mt][nt][2] + b0, acc[mt][nt][3] + b1);
        }
    }
}

__global__ __launch_bounds__(128, 2) void qkv_gemm_tc(const float* __restrict__ A,
                                                      const float* __restrict__ W0,
                                                      const float* __restrict__ W1,
                                                      const float* __restrict__ W2) {
    extern __shared__ float dsm[];
    const float* W = (blockIdx.z == 0) ? W0 : (blockIdx.z == 1) ? W1 : W2;
    float* C = (blockIdx.z == 0) ? g_Q : (blockIdx.z == 1) ? g_K : g_V;
    gemm_body(A, W, C, nullptr, blockIdx.y * 128, blockIdx.x * 128, dsm);
}

__global__ __launch_bounds__(128, 2) void out_gemm_tc(const float* __restrict__ Wo,
                                                      const float* __restrict__ bo,
                                                      float* __restrict__ Out) {
    extern __shared__ float dsm[];
    gemm_body(g_C, Wo, Out, bo, blockIdx.y * 128, blockIdx.x * 128, dsm);
}

// ---------------- tensor-core flash attention (unchanged) --------------------
#define AQS 0
#define AKS 8704
#define AVS 13056
#define APS 17664
#define ATT_SMEM_U32 26368
#define ATT_SMEM_BYTES (ATT_SMEM_U32 * 4)

__global__ __launch_bounds__(256) void attn_tc_kernel() {
    extern __shared__ uint32_t sm[];
    uint32_t* Qs = sm + AQS;
    uint32_t* Ks = sm + AKS;
    uint32_t* Vs = sm + AVS;
    uint32_t* Ps = sm + APS;

    const int b = blockIdx.z;
    const int h = blockIdx.y;
    const int q0 = blockIdx.x * 128;
    const int len = g_len[b];
    const int tid = threadIdx.x;
    const int lane = tid & 31;
    const int wid = tid >> 5;
    const int wm = wid * 16;
    const int r = lane >> 2;
    const int c = lane & 3;

#pragma unroll
    for (int i = 0; i < 8; i++) {
        int idx = tid + i * 256;
        int rr = idx >> 4, c4 = (idx & 15) * 4;
        float4 v = *(const float4*)(g_Q + ((size_t)(b * NN + q0 + rr) * DOUT) + h * HD + c4);
        uint4 u = make_uint4(f2tf32(v.x), f2tf32(v.y), f2tf32(v.z), f2tf32(v.w));
        *(uint4*)(Qs + rr * 68 + c4) = u;
    }

    float oacc[8][4];
#pragma unroll
    for (int nd = 0; nd < 8; nd++)
#pragma unroll
        for (int i = 0; i < 4; i++) oacc[nd][i] = 0.f;
    float m0 = -CUDART_INF_F, m1 = -CUDART_INF_F;
    float l0 = 0.f, l1 = 0.f;

    const int qrow0 = q0 + wm + r;
    const int qrow1 = qrow0 + 8;
    const int kv_end = min(q0 + 128, len);

    for (int j0 = 0; j0 < kv_end; j0 += 64) {
        __syncthreads();
#pragma unroll
        for (int i = 0; i < 4; i++) {
            int idx = tid + i * 256;
            int key = idx >> 4, c4 = (idx & 15) * 4;
            size_t g = ((size_t)(b * NN + j0 + key) * DOUT) + h * HD + c4;
            float4 kv = *(const float4*)(g_K + g);
            float4 vv = *(const float4*)(g_V + g);
            *(uint4*)(Ks + key * 68 + c4) =
                make_uint4(f2tf32(kv.x), f2tf32(kv.y), f2tf32(kv.z), f2tf32(kv.w));
            *(uint4*)(Vs + key * 72 + c4) =
                make_uint4(f2tf32(vv.x), f2tf32(vv.y), f2tf32(vv.z), f2tf32(vv.w));
        }
        __syncthreads();

        float sacc[8][4];
#pragma unroll
        for (int nt = 0; nt < 8; nt++)
#pragma unroll
            for (int i = 0; i < 4; i++) sacc[nt][i] = 0.f;
#pragma unroll
        for (int ks = 0; ks < 64; ks += 8) {
            uint32_t af[4];
            af[0] = Qs[(wm + r) * 68 + ks + c];
            af[1] = Qs[(wm + r + 8) * 68 + ks + c];
            af[2] = Qs[(wm + r) * 68 + ks + c + 4];
            af[3] = Qs[(wm + r + 8) * 68 + ks + c + 4];
#pragma unroll
            for (int nt = 0; nt < 8; nt++) {
                uint32_t bf[2];
                bf[0] = Ks[(nt * 8 + r) * 68 + ks + c];
                bf[1] = Ks[(nt * 8 + r) * 68 + ks + c + 4];
                mma_tf32(sacc[nt], af, bf);
            }
        }

        float mx0 = -CUDART_INF_F, mx1 = -CUDART_INF_F;
#pragma unroll
        for (int nt = 0; nt < 8; nt++) {
            int k0i = j0 + nt * 8 + 2 * c;
            int k1i = k0i + 1;
            float s0 = sacc[nt][0] * 0.125f;
            float s1 = sacc[nt][1] * 0.125f;
            float s2 = sacc[nt][2] * 0.125f;
            float s3 = sacc[nt][3] * 0.125f;
            if (k0i > qrow0 || k0i >= len) s0 = -CUDART_INF_F;
            if (k1i > qrow0 || k1i >= len) s1 = -CUDART_INF_F;
            if (k0i > qrow1 || k0i >= len) s2 = -CUDART_INF_F;
            if (k1i > qrow1 || k1i >= len) s3 = -CUDART_INF_F;
            sacc[nt][0] = s0; sacc[nt][1] = s1; sacc[nt][2] = s2; sacc[nt][3] = s3;
            mx0 = fmaxf(mx0, fmaxf(s0, s1));
            mx1 = fmaxf(mx1, fmaxf(s2, s3));
        }
        mx0 = fmaxf(mx0, __shfl_xor_sync(0xffffffffu, mx0, 1));
        mx0 = fmaxf(mx0, __shfl_xor_sync(0xffffffffu, mx0, 2));
        mx1 = fmaxf(mx1, __shfl_xor_sync(0xffffffffu, mx1, 1));
        mx1 = fmaxf(mx1, __shfl_xor_sync(0xffffffffu, mx1, 2));

        float mn0 = fmaxf(m0, mx0);
        float mn1 = fmaxf(m1, mx1);
        float corr0 = __expf(m0 - mn0);
        float corr1 = __expf(m1 - mn1);

        float sum0 = 0.f, sum1 = 0.f;
#pragma unroll
        for (int nt = 0; nt < 8; nt++) {
            float p0 = __expf(sacc[nt][0] - mn0);
            float p1 = __expf(sacc[nt][1] - mn0);
            float p2 = __expf(sacc[nt][2] - mn1);
            float p3 = __expf(sacc[nt][3] - mn1);
            sum0 += p0 + p1;
            sum1 += p2 + p3;
            *(uint2*)(Ps + (wm + r) * 68 + nt * 8 + 2 * c) =
                make_uint2(f2tf32(p0), f2tf32(p1));
            *(uint2*)(Ps + (wm + r + 8) * 68 + nt * 8 + 2 * c) =
                make_uint2(f2tf32(p2), f2tf32(p3));
        }
        sum0 += __shfl_xor_sync(0xffffffffu, sum0, 1);
        sum0 += __shfl_xor_sync(0xffffffffu, sum0, 2);
        sum1 += __shfl_xor_sync(0xffffffffu, sum1, 1);
        sum1 += __shfl_xor_sync(0xffffffffu, sum1, 2);
        l0 = l0 * corr0 + sum0;
        l1 = l1 * corr1 + sum1;
        m0 = mn0;
        m1 = mn1;
#pragma unroll
        for (int nd = 0; nd < 8; nd++) {
            oacc[nd][0] *= corr0; oacc[nd][1] *= corr0;
            oacc[nd][2] *= corr1; oacc[nd][3] *= corr1;
        }
        __syncwarp();

#pragma unroll
        for (int ks = 0; ks < 64; ks += 8) {
            uint32_t af[4];
            af[0] = Ps[(wm + r) * 68 + ks + c];
            af[1] = Ps[(wm + r + 8) * 68 + ks + c];
            af[2] = Ps[(wm + r) * 68 + ks + c + 4];
            af[3] = Ps[(wm + r + 8) * 68 + ks + c + 4];
#pragma unroll
            for (int nd = 0; nd < 8; nd++) {
                uint32_t bf[2];
                bf[0] = Vs[(ks + c) * 72 + nd * 8 + r];
                bf[1] = Vs[(ks + c + 4) * 72 + nd * 8 + r];
                mma_tf32(oacc[nd], af, bf);
            }
        }
    }

    float inv0 = 1.f / l0;
    float inv1 = 1.f / l1;
    float* out0 = g_C + ((size_t)(b * NN + qrow0) * DOUT) + h * HD;
    float* out1 = g_C + ((size_t)(b * NN + qrow1) * DOUT) + h * HD;
#pragma unroll
    for (int nd = 0; nd < 8; nd++) {
        int col = nd * 8 + 2 * c;
        *(float2*)(out0 + col) = make_float2(oacc[nd][0] * inv0, oacc[nd][1] * inv0);
        *(float2*)(out1 + col) = make_float2(oacc[nd][2] * inv1, oacc[nd][3] * inv1);
    }
}

// ---------------- launch ------------------------------------------------------
extern "C" void kernel_launch(void* const* d_in, const int* in_sizes, int n_in,
                              void* d_out, int out_size) {
    const float* x    = (const float*)d_in[0];
    const int*   mask = (const int*)d_in[1];
    const float* Wq   = (const float*)d_in[2];
    const float* Wk   = (const float*)d_in[3];
    const float* Wv   = (const float*)d_in[4];
    const float* Wo   = (const float*)d_in[5];
    const float* bo   = (const float*)d_in[6];
    float* out = (float*)d_out;

    cudaFuncSetAttribute(attn_tc_kernel,
                         cudaFuncAttributeMaxDynamicSharedMemorySize, ATT_SMEM_BYTES);
    cudaFuncSetAttribute(qkv_gemm_tc,
                         cudaFuncAttributeMaxDynamicSharedMemorySize, GEMM_SMEM_BYTES);
    cudaFuncSetAttribute(out_gemm_tc,
                         cudaFuncAttributeMaxDynamicSharedMemorySize, GEMM_SMEM_BYTES);

    len_kernel<<<BB, 256>>>(mask);

    dim3 gq(DOUT / 128, MTOT / 128, 3);
    qkv_gemm_tc<<<gq, 128, GEMM_SMEM_BYTES>>>(x, Wq, Wk, Wv);

    dim3 ga(NN / 128, NH, BB);
    attn_tc_kernel<<<ga, 256, ATT_SMEM_BYTES>>>();

    dim3 go(DOUT / 128, MTOT / 128, 1);
    out_gemm_tc<<<go, 128, GEMM_SMEM_BYTES>>>(Wo, bo, out);
}

// round 8
// speedup vs baseline: 7.3799x; 1.0018x over previous
#include <cuda_runtime.h>
#include <cuda_bf16.h>
#include <math_constants.h>
#include <cstdint>

#define BB 4
#define NN 2048
#define DIN 1024
#define DOUT 1024
#define NH 16
#define HD 64
#define MTOT (BB * NN)

// scratch
__device__ float    g_Q[MTOT * DOUT];
__device__ float    g_K[MTOT * DOUT];
__device__ float    g_V[MTOT * DOUT];
__device__ uint32_t g_Xp[MTOT * DIN];        // x, A-fragment-permuted tf32
__device__ uint32_t g_Cp[MTOT * DOUT];       // attn out, A-fragment-permuted tf32
__device__ uint32_t g_Wqp[DIN * DOUT];       // weights, B-fragment-permuted tf32
__device__ uint32_t g_Wkp[DIN * DOUT];
__device__ uint32_t g_Wvp[DIN * DOUT];
__device__ uint32_t g_Wop[DIN * DOUT];
__device__ int      g_len[BB];

// ---------------- per-batch valid length ------------------------------------
__global__ void len_kernel(const int* __restrict__ mask) {
    int b = blockIdx.x;
    int s = 0;
    for (int i = threadIdx.x; i < NN; i += 256) s += mask[b * NN + i];
    __shared__ int sh[256];
    sh[threadIdx.x] = s;
    __syncthreads();
    for (int off = 128; off; off >>= 1) {
        if (threadIdx.x < off) sh[threadIdx.x] += sh[threadIdx.x + off];
        __syncthreads();
    }
    if (threadIdx.x == 0) g_len[b] = sh[0];
}

// ---------------- helpers ----------------------------------------------------
__device__ __forceinline__ uint32_t f2tf32(float f) {
    uint32_t u;
    asm("cvt.rna.tf32.f32 %0, %1;" : "=r"(u) : "f"(f));
    return u;
}
__device__ __forceinline__ void mma_tf32(float* d, const uint32_t* a, const uint32_t* b) {
    asm volatile(
        "mma.sync.aligned.m16n8k8.row.col.f32.tf32.tf32.f32 "
        "{%0,%1,%2,%3}, {%4,%5,%6,%7}, {%8,%9}, {%0,%1,%2,%3};"
        : "+f"(d[0]), "+f"(d[1]), "+f"(d[2]), "+f"(d[3])
        : "r"(a[0]), "r"(a[1]), "r"(a[2]), "r"(a[3]), "r"(b[0]), "r"(b[1]));
}
__device__ __forceinline__ void cp16(void* s, const void* g) {
    uint32_t sa = (uint32_t)__cvta_generic_to_shared(s);
    asm volatile("cp.async.ca.shared.global [%0], [%1], 16;" :: "r"(sa), "l"(g));
}
#define CP_COMMIT() asm volatile("cp.async.commit_group;" ::: "memory")
#define CP_WAIT0()  asm volatile("cp.async.wait_group 0;" ::: "memory")

// ---------------- operand permute kernels ------------------------------------
// A-perm: [mt (M/16)][kt (K/8)] blocks of 128 u32 = [lane][4]:
//   a0=A[mt16+r][kt8+c] a1=[+8][c] a2=[r][c+4] a3=[+8][c+4], lane=(r<<2)|c
__global__ __launch_bounds__(256) void perm_a_kernel(const float* __restrict__ A,
                                                     uint32_t* __restrict__ Ap) {
    int gw = blockIdx.x * 8 + (threadIdx.x >> 5);   // block index over (mt,kt)
    int lane = threadIdx.x & 31;
    int mt = gw >> 7, kt = gw & 127;
    int r = lane >> 2, c = lane & 3;
    const float* base = A + (size_t)(mt * 16) * DIN + kt * 8;
    uint4 u;
    u.x = f2tf32(base[r * DIN + c]);
    u.y = f2tf32(base[(r + 8) * DIN + c]);
    u.z = f2tf32(base[r * DIN + c + 4]);
    u.w = f2tf32(base[(r + 8) * DIN + c + 4]);
    *(uint4*)(Ap + ((size_t)gw * 32 + lane) * 4) = u;
}

// B-perm: [nt (N/8)][kt (K/8)] blocks of 64 u32 = [lane][2]:
//   b0=W[kt8+c][nt8+r]  b1=W[kt8+c+4][nt8+r]
__global__ __launch_bounds__(256) void perm_w_kernel(const float* __restrict__ W0,
                                                     const float* __restrict__ W1,
                                                     const float* __restrict__ W2,
                                                     const float* __restrict__ W3) {
    const float* W = (blockIdx.y == 0) ? W0 : (blockIdx.y == 1) ? W1
                    : (blockIdx.y == 2) ? W2 : W3;
    uint32_t* Wp = (blockIdx.y == 0) ? g_Wqp : (blockIdx.y == 1) ? g_Wkp
                  : (blockIdx.y == 2) ? g_Wvp : g_Wop;
    int gw = blockIdx.x * 8 + (threadIdx.x >> 5);
    int lane = threadIdx.x & 31;
    int nt = gw >> 7, kt = gw & 127;
    int r = lane >> 2, c = lane & 3;
    uint2 u;
    u.x = f2tf32(W[(size_t)(kt * 8 + c) * DOUT + nt * 8 + r]);
    u.y = f2tf32(W[(size_t)(kt * 8 + c + 4) * DOUT + nt * 8 + r]);
    *(uint2*)(Wp + (size_t)gw * 64 + lane * 2) = u;
}

// ---------------- tf32 GEMM on permuted operands -----------------------------
// 128 threads, 4 warps 2x2, 64x64 warp tiles, tile 128x128x32.
#define ASTAGE 4096                     // u32: 8 mt x 4 kt x 128
#define BSTAGE 4096                     // u32: 16 nt x 4 kt x 64
#define GSTAGE2 (ASTAGE + BSTAGE)       // 8192 u32 = 32KB
#define GEMM_SMEM_BYTES (2 * GSTAGE2 * 4)   // 64KB

__device__ __forceinline__ void gemm_body(const uint32_t* __restrict__ Ap,
                                          const uint32_t* __restrict__ Wp,
                                          float* __restrict__ C,
                                          const float* __restrict__ bias,
                                          int bm, int bn, uint32_t* dsm) {
    const int tid = threadIdx.x;
    const int lane = tid & 31;
    const int wid = tid >> 5;
    const int wm = (wid >> 1) * 64;
    const int wn = (wid & 1) * 64;
    const int mtb = (wid >> 1) * 4;     // local A-block base
    const int ntb = (wid & 1) * 8;      // local B-block base
    const int r = lane >> 2;
    const int c = lane & 3;
    const int mt0 = bm >> 4;
    const int nt0 = bn >> 3;

    float acc[4][8][4];
#pragma unroll
    for (int mt = 0; mt < 4; mt++)
#pragma unroll
        for (int nt = 0; nt < 8; nt++)
#pragma unroll
            for (int i = 0; i < 4; i++) acc[mt][nt][i] = 0.f;

    auto load_stage = [&](int s, int kb) {   // kb: k-block (8-wide) index, mult of 4
        uint32_t* Asm = dsm + s * GSTAGE2;
        uint32_t* Bsm = Asm + ASTAGE;
#pragma unroll
        for (int i = 0; i < 8; i++) {        // 1024 cp16 for A
            int f = tid + i * 128;
            int mtL = f >> 7, rem = f & 127;
            cp16(Asm + mtL * 512 + rem * 4,
                 Ap + ((size_t)(mt0 + mtL) * 128 + kb) * 128 + rem * 4);
        }
#pragma unroll
        for (int i = 0; i < 8; i++) {        // 1024 cp16 for B
            int f = tid + i * 128;
            int ntL = f >> 6, rem = f & 63;
            cp16(Bsm + ntL * 256 + rem * 4,
                 Wp + ((size_t)(nt0 + ntL) * 128 + kb) * 64 + rem * 4);
        }
    };

    load_stage(0, 0);
    CP_COMMIT();

    for (int kt = 0; kt < 32; kt++) {
        CP_WAIT0();
        __syncthreads();
        if (kt + 1 < 32) {
            load_stage((kt + 1) & 1, (kt + 1) * 4);
            CP_COMMIT();
        }
        const uint32_t* Asm = dsm + (kt & 1) * GSTAGE2;
        const uint32_t* Bsm = Asm + ASTAGE;

#pragma unroll
        for (int ktL = 0; ktL < 4; ktL++) {
            uint32_t af[4][4];
#pragma unroll
            for (int mtL = 0; mtL < 4; mtL++) {
                uint4 t = *(const uint4*)(Asm + ((mtb + mtL) * 4 + ktL) * 128 + lane * 4);
                af[mtL][0] = t.x; af[mtL][1] = t.y; af[mtL][2] = t.z; af[mtL][3] = t.w;
            }
            uint32_t bf[8][2];
#pragma unroll
            for (int ntL = 0; ntL < 8; ntL++) {
                uint2 t = *(const uint2*)(Bsm + (ntb + ntL) * 256 + ktL * 64 + lane * 2);
                bf[ntL][0] = t.x; bf[ntL][1] = t.y;
            }
#pragma unroll
            for (int mtL = 0; mtL < 4; mtL++)
#pragma unroll
                for (int ntL = 0; ntL < 8; ntL++)
                    mma_tf32(acc[mtL][ntL], af[mtL], bf[ntL]);
        }
        __syncthreads();
    }

    // epilogue (plain f32 rows)
#pragma unroll
    for (int mt = 0; mt < 4; mt++) {
        int row0 = bm + wm + mt * 16 + r;
        int row1 = row0 + 8;
#pragma unroll
        for (int nt = 0; nt < 8; nt++) {
            int col = bn + wn + nt * 8 + c * 2;
            float b0 = bias ? bias[col] : 0.f;
            float b1 = bias ? bias[col + 1] : 0.f;
            *(float2*)(C + (size_t)row0 * DOUT + col) =
                make_float2(acc[mt][nt][0] + b0, acc[mt][nt][1] + b1);
            *(float2*)(C + (size_t)row1 * DOUT + col) =
                make_float2(acc[mt][nt][2] + b0, acc[mt][nt][3] + b1);
        }
    }
}

__global__ __launch_bounds__(128, 2) void qkv_gemm_tc() {
    extern __shared__ uint32_t dsm[];
    const uint32_t* Wp = (blockIdx.z == 0) ? g_Wqp : (blockIdx.z == 1) ? g_Wkp : g_Wvp;
    float* C = (blockIdx.z == 0) ? g_Q : (blockIdx.z == 1) ? g_K : g_V;
    gemm_body(g_Xp, Wp, C, nullptr, blockIdx.y * 128, blockIdx.x * 128, dsm);
}

__global__ __launch_bounds__(128, 2) void out_gemm_tc(const float* __restrict__ bo,
                                                      float* __restrict__ Out) {
    extern __shared__ uint32_t dsm[];
    gemm_body(g_Cp, g_Wop, Out, bo, blockIdx.y * 128, blockIdx.x * 128, dsm);
}

// ---------------- tensor-core flash attention --------------------------------
#define AQS 0
#define AKS 8704
#define AVS 13056
#define APS 17664
#define ATT_SMEM_U32 26368
#define ATT_SMEM_BYTES (ATT_SMEM_U32 * 4)

__global__ __launch_bounds__(256) void attn_tc_kernel() {
    extern __shared__ uint32_t sm[];
    uint32_t* Qs = sm + AQS;
    uint32_t* Ks = sm + AKS;
    uint32_t* Vs = sm + AVS;
    uint32_t* Ps = sm + APS;

    const int b = blockIdx.z;
    const int h = blockIdx.y;
    const int q0 = blockIdx.x * 128;
    const int len = g_len[b];
    const int tid = threadIdx.x;
    const int lane = tid & 31;
    const int wid = tid >> 5;
    const int wm = wid * 16;
    const int r = lane >> 2;
    const int c = lane & 3;

#pragma unroll
    for (int i = 0; i < 8; i++) {
        int idx = tid + i * 256;
        int rr = idx >> 4, c4 = (idx & 15) * 4;
        float4 v = *(const float4*)(g_Q + ((size_t)(b * NN + q0 + rr) * DOUT) + h * HD + c4);
        uint4 u = make_uint4(f2tf32(v.x), f2tf32(v.y), f2tf32(v.z), f2tf32(v.w));
        *(uint4*)(Qs + rr * 68 + c4) = u;
    }

    float oacc[8][4];
#pragma unroll
    for (int nd = 0; nd < 8; nd++)
#pragma unroll
        for (int i = 0; i < 4; i++) oacc[nd][i] = 0.f;
    float m0 = -CUDART_INF_F, m1 = -CUDART_INF_F;
    float l0 = 0.f, l1 = 0.f;

    const int qrow0 = q0 + wm + r;
    const int qrow1 = qrow0 + 8;
    const int kv_end = min(q0 + 128, len);

    for (int j0 = 0; j0 < kv_end; j0 += 64) {
        __syncthreads();
#pragma unroll
        for (int i = 0; i < 4; i++) {
            int idx = tid + i * 256;
            int key = idx >> 4, c4 = (idx & 15) * 4;
            size_t g = ((size_t)(b * NN + j0 + key) * DOUT) + h * HD + c4;
            float4 kv = *(const float4*)(g_K + g);
            float4 vv = *(const float4*)(g_V + g);
            *(uint4*)(Ks + key * 68 + c4) =
                make_uint4(f2tf32(kv.x), f2tf32(kv.y), f2tf32(kv.z), f2tf32(kv.w));
            *(uint4*)(Vs + key * 72 + c4) =
                make_uint4(f2tf32(vv.x), f2tf32(vv.y), f2tf32(vv.z), f2tf32(vv.w));
        }
        __syncthreads();

        float sacc[8][4];
#pragma unroll
        for (int nt = 0; nt < 8; nt++)
#pragma unroll
            for (int i = 0; i < 4; i++) sacc[nt][i] = 0.f;
#pragma unroll
        for (int ks = 0; ks < 64; ks += 8) {
            uint32_t af[4];
            af[0] = Qs[(wm + r) * 68 + ks + c];
            af[1] = Qs[(wm + r + 8) * 68 + ks + c];
            af[2] = Qs[(wm + r) * 68 + ks + c + 4];
            af[3] = Qs[(wm + r + 8) * 68 + ks + c + 4];
#pragma unroll
            for (int nt = 0; nt < 8; nt++) {
                uint32_t bf[2];
                bf[0] = Ks[(nt * 8 + r) * 68 + ks + c];
                bf[1] = Ks[(nt * 8 + r) * 68 + ks + c + 4];
                mma_tf32(sacc[nt], af, bf);
            }
        }

        float mx0 = -CUDART_INF_F, mx1 = -CUDART_INF_F;
#pragma unroll
        for (int nt = 0; nt < 8; nt++) {
            int k0i = j0 + nt * 8 + 2 * c;
            int k1i = k0i + 1;
            float s0 = sacc[nt][0] * 0.125f;
            float s1 = sacc[nt][1] * 0.125f;
            float s2 = sacc[nt][2] * 0.125f;
            float s3 = sacc[nt][3] * 0.125f;
            if (k0i > qrow0 || k0i >= len) s0 = -CUDART_INF_F;
            if (k1i > qrow0 || k1i >= len) s1 = -CUDART_INF_F;
            if (k0i > qrow1 || k0i >= len) s2 = -CUDART_INF_F;
            if (k1i > qrow1 || k1i >= len) s3 = -CUDART_INF_F;
            sacc[nt][0] = s0; sacc[nt][1] = s1; sacc[nt][2] = s2; sacc[nt][3] = s3;
            mx0 = fmaxf(mx0, fmaxf(s0, s1));
            mx1 = fmaxf(mx1, fmaxf(s2, s3));
        }
        mx0 = fmaxf(mx0, __shfl_xor_sync(0xffffffffu, mx0, 1));
        mx0 = fmaxf(mx0, __shfl_xor_sync(0xffffffffu, mx0, 2));
        mx1 = fmaxf(mx1, __shfl_xor_sync(0xffffffffu, mx1, 1));
        mx1 = fmaxf(mx1, __shfl_xor_sync(0xffffffffu, mx1, 2));

        float mn0 = fmaxf(m0, mx0);
        float mn1 = fmaxf(m1, mx1);
        float corr0 = __expf(m0 - mn0);
        float corr1 = __expf(m1 - mn1);

        float sum0 = 0.f, sum1 = 0.f;
#pragma unroll
        for (int nt = 0; nt < 8; nt++) {
            float p0 = __expf(sacc[nt][0] - mn0);
            float p1 = __expf(sacc[nt][1] - mn0);
            float p2 = __expf(sacc[nt][2] - mn1);
            float p3 = __expf(sacc[nt][3] - mn1);
            sum0 += p0 + p1;
            sum1 += p2 + p3;
            *(uint2*)(Ps + (wm + r) * 68 + nt * 8 + 2 * c) =
                make_uint2(f2tf32(p0), f2tf32(p1));
            *(uint2*)(Ps + (wm + r + 8) * 68 + nt * 8 + 2 * c) =
                make_uint2(f2tf32(p2), f2tf32(p3));
        }
        sum0 += __shfl_xor_sync(0xffffffffu, sum0, 1);
        sum0 += __shfl_xor_sync(0xffffffffu, sum0, 2);
        sum1 += __shfl_xor_sync(0xffffffffu, sum1, 1);
        sum1 += __shfl_xor_sync(0xffffffffu, sum1, 2);
        l0 = l0 * corr0 + sum0;
        l1 = l1 * corr1 + sum1;
        m0 = mn0;
        m1 = mn1;
#pragma unroll
        for (int nd = 0; nd < 8; nd++) {
            oacc[nd][0] *= corr0; oacc[nd][1] *= corr0;
            oacc[nd][2] *= corr1; oacc[nd][3] *= corr1;
        }
        __syncwarp();

#pragma unroll
        for (int ks = 0; ks < 64; ks += 8) {
            uint32_t af[4];
            af[0] = Ps[(wm + r) * 68 + ks + c];
            af[1] = Ps[(wm + r + 8) * 68 + ks + c];
            af[2] = Ps[(wm + r) * 68 + ks + c + 4];
            af[3] = Ps[(wm + r + 8) * 68 + ks + c + 4];
#pragma unroll
            for (int nd = 0; nd < 8; nd++) {
                uint32_t bf[2];
                bf[0] = Vs[(ks + c) * 72 + nd * 8 + r];
                bf[1] = Vs[(ks + c + 4) * 72 + nd * 8 + r];
                mma_tf32(oacc[nd], af, bf);
            }
        }
    }

    // ---- epilogue: write A-fragment-permuted tf32 directly into g_Cp ----
    // rows qrow0 (i-even) / qrow1 (i-odd) live in the same 16-row tile.
    float inv0 = 1.f / l0;
    float inv1 = 1.f / l1;
    const int mt = (b * NN + q0 + wm) >> 4;           // 16-row tile index
    const int laneA = r * 4 + ((2 * c) & 3);
    const int laneB = r * 4 + ((2 * c + 1) & 3);
    const int i0 = 2 * (c >> 1);
#pragma unroll
    for (int nd = 0; nd < 8; nd++) {
        int ktc = h * 8 + nd;                          // 8-col tile index
        uint32_t* base = g_Cp + ((size_t)mt * 128 + ktc) * 128;
        base[laneA * 4 + i0]     = f2tf32(oacc[nd][0] * inv0);
        base[laneB * 4 + i0]     = f2tf32(oacc[nd][1] * inv0);
        base[laneA * 4 + i0 + 1] = f2tf32(oacc[nd][2] * inv1);
        base[laneB * 4 + i0 + 1] = f2tf32(oacc[nd][3] * inv1);
    }
}

// ---------------- launch ------------------------------------------------------
extern "C" void kernel_launch(void* const* d_in, const int* in_sizes, int n_in,
                              void* d_out, int out_size) {
    const float* x    = (const float*)d_in[0];
    const int*   mask = (const int*)d_in[1];
    const float* Wq   = (const float*)d_in[2];
    const float* Wk   = (const float*)d_in[3];
    const float* Wv   = (const float*)d_in[4];
    const float* Wo   = (const float*)d_in[5];
    const float* bo   = (const float*)d_in[6];
    float* out = (float*)d_out;

    cudaFuncSetAttribute(attn_tc_kernel,
                         cudaFuncAttributeMaxDynamicSharedMemorySize, ATT_SMEM_BYTES);
    cudaFuncSetAttribute(qkv_gemm_tc,
                         cudaFuncAttributeMaxDynamicSharedMemorySize, GEMM_SMEM_BYTES);
    cudaFuncSetAttribute(out_gemm_tc,
                         cudaFuncAttributeMaxDynamicSharedMemorySize, GEMM_SMEM_BYTES);

    len_kernel<<<BB, 256>>>(mask);

    uint32_t* xp;
    cudaGetSymbolAddress((void**)&xp, g_Xp);
    perm_a_kernel<<<(MTOT / 16) * (DIN / 8) / 8, 256>>>(x, xp);

    dim3 gw(2048, 4);
    perm_w_kernel<<<gw, 256>>>(Wq, Wk, Wv, Wo);

    dim3 gq(DOUT / 128, MTOT / 128, 3);
    qkv_gemm_tc<<<gq, 128, GEMM_SMEM_BYTES>>>();

    dim3 ga(NN / 128, NH, BB);
    attn_tc_kernel<<<ga, 256, ATT_SMEM_BYTES>>>();

    dim3 go(DOUT / 128, MTOT / 128, 1);
    out_gemm_tc<<<go, 128, GEMM_SMEM_BYTES>>>(bo, out);
}

// round 9
// speedup vs baseline: 7.3899x; 1.0014x over previous
#include <cuda_runtime.h>
#include <cuda_bf16.h>
#include <math_constants.h>
#include <cstdint>

#define BB 4
#define NN 2048
#define DIN 1024
#define DOUT 1024
#define NH 16
#define HD 64
#define MTOT (BB * NN)

// fragment-permuted tf32 scratch
__device__ uint32_t g_Xp[MTOT * DIN];    // x   : A-frag [mtG][ktG][128]
__device__ uint32_t g_Qp[MTOT * DOUT];   // Q   : A-frag [mtG][ktG][128]
__device__ uint32_t g_Kp[MTOT * DOUT];   // K   : B-frag [ntG=key/8][ktG=dim/8][64]
__device__ uint32_t g_Vp[MTOT * DOUT];   // V   : B-frag [ntG=dim/8][ktG=key/8][64]
__device__ uint32_t g_Cp[MTOT * DOUT];   // attn out: A-frag
__device__ uint32_t g_Wqp[DIN * DOUT];   // weights: B-frag [ntG][ktG][64]
__device__ uint32_t g_Wkp[DIN * DOUT];
__device__ uint32_t g_Wvp[DIN * DOUT];
__device__ uint32_t g_Wop[DIN * DOUT];
__device__ int      g_len[BB];

// ---------------- per-batch valid length ------------------------------------
__global__ void len_kernel(const int* __restrict__ mask) {
    int b = blockIdx.x;
    int s = 0;
    for (int i = threadIdx.x; i < NN; i += 256) s += mask[b * NN + i];
    __shared__ int sh[256];
    sh[threadIdx.x] = s;
    __syncthreads();
    for (int off = 128; off; off >>= 1) {
        if (threadIdx.x < off) sh[threadIdx.x] += sh[threadIdx.x + off];
        __syncthreads();
    }
    if (threadIdx.x == 0) g_len[b] = sh[0];
}

// ---------------- helpers ----------------------------------------------------
__device__ __forceinline__ uint32_t f2tf32(float f) {
    uint32_t u;
    asm("cvt.rna.tf32.f32 %0, %1;" : "=r"(u) : "f"(f));
    return u;
}
__device__ __forceinline__ void mma_tf32(float* d, const uint32_t* a, const uint32_t* b) {
    asm volatile(
        "mma.sync.aligned.m16n8k8.row.col.f32.tf32.tf32.f32 "
        "{%0,%1,%2,%3}, {%4,%5,%6,%7}, {%8,%9}, {%0,%1,%2,%3};"
        : "+f"(d[0]), "+f"(d[1]), "+f"(d[2]), "+f"(d[3])
        : "r"(a[0]), "r"(a[1]), "r"(a[2]), "r"(a[3]), "r"(b[0]), "r"(b[1]));
}
__device__ __forceinline__ void cp16(void* s, const void* g) {
    uint32_t sa = (uint32_t)__cvta_generic_to_shared(s);
    asm volatile("cp.async.ca.shared.global [%0], [%1], 16;" :: "r"(sa), "l"(g));
}
#define CP_COMMIT() asm volatile("cp.async.commit_group;" ::: "memory")
#define CP_WAIT0()  asm volatile("cp.async.wait_group 0;" ::: "memory")

// ---------------- operand permute kernels ------------------------------------
__global__ __launch_bounds__(256) void perm_a_kernel(const float* __restrict__ A,
                                                     uint32_t* __restrict__ Ap) {
    int gw = blockIdx.x * 8 + (threadIdx.x >> 5);
    int lane = threadIdx.x & 31;
    int mt = gw >> 7, kt = gw & 127;
    int r = lane >> 2, c = lane & 3;
    const float* base = A + (size_t)(mt * 16) * DIN + kt * 8;
    uint4 u;
    u.x = f2tf32(base[r * DIN + c]);
    u.y = f2tf32(base[(r + 8) * DIN + c]);
    u.z = f2tf32(base[r * DIN + c + 4]);
    u.w = f2tf32(base[(r + 8) * DIN + c + 4]);
    *(uint4*)(Ap + ((size_t)gw * 32 + lane) * 4) = u;
}

__global__ __launch_bounds__(256) void perm_w_kernel(const float* __restrict__ W0,
                                                     const float* __restrict__ W1,
                                                     const float* __restrict__ W2,
                                                     const float* __restrict__ W3) {
    const float* W = (blockIdx.y == 0) ? W0 : (blockIdx.y == 1) ? W1
                    : (blockIdx.y == 2) ? W2 : W3;
    uint32_t* Wp = (blockIdx.y == 0) ? g_Wqp : (blockIdx.y == 1) ? g_Wkp
                  : (blockIdx.y == 2) ? g_Wvp : g_Wop;
    int gw = blockIdx.x * 8 + (threadIdx.x >> 5);
    int lane = threadIdx.x & 31;
    int nt = gw >> 7, kt = gw & 127;
    int r = lane >> 2, c = lane & 3;
    uint2 u;
    u.x = f2tf32(W[(size_t)(kt * 8 + c) * DOUT + nt * 8 + r]);
    u.y = f2tf32(W[(size_t)(kt * 8 + c + 4) * DOUT + nt * 8 + r]);
    *(uint2*)(Wp + (size_t)gw * 64 + lane * 2) = u;
}

// ---------------- tf32 GEMM on permuted operands -----------------------------
// 128 threads, 4 warps 2x2, 64x64 warp tiles, tile 128x128x32.
// epi: 0 = f32 rows (+bias) -> C ; 1 = A-frag -> g_Qp ; 2 = B-frag -> g_Kp ;
//      3 = B-frag (PV orientation) -> g_Vp
#define ASTAGE 4096
#define BSTAGE 4096
#define GSTAGE2 (ASTAGE + BSTAGE)
#define GEMM_SMEM_BYTES (2 * GSTAGE2 * 4)

__device__ __forceinline__ void gemm_body(const uint32_t* __restrict__ Ap,
                                          const uint32_t* __restrict__ Wp,
                                          float* __restrict__ C,
                                          const float* __restrict__ bias,
                                          int bm, int bn, uint32_t* dsm, int epi) {
    const int tid = threadIdx.x;
    const int lane = tid & 31;
    const int wid = tid >> 5;
    const int wm = (wid >> 1) * 64;
    const int wn = (wid & 1) * 64;
    const int mtb = (wid >> 1) * 4;
    const int ntb = (wid & 1) * 8;
    const int r = lane >> 2;
    const int c = lane & 3;
    const int mt0 = bm >> 4;
    const int nt0 = bn >> 3;

    float acc[4][8][4];
#pragma unroll
    for (int mt = 0; mt < 4; mt++)
#pragma unroll
        for (int nt = 0; nt < 8; nt++)
#pragma unroll
            for (int i = 0; i < 4; i++) acc[mt][nt][i] = 0.f;

    auto load_stage = [&](int s, int kb) {
        uint32_t* Asm = dsm + s * GSTAGE2;
        uint32_t* Bsm = Asm + ASTAGE;
#pragma unroll
        for (int i = 0; i < 8; i++) {
            int f = tid + i * 128;
            int mtL = f >> 7, rem = f & 127;
            cp16(Asm + mtL * 512 + rem * 4,
                 Ap + ((size_t)(mt0 + mtL) * 128 + kb) * 128 + rem * 4);
        }
#pragma unroll
        for (int i = 0; i < 8; i++) {
            int f = tid + i * 128;
            int ntL = f >> 6, rem = f & 63;
            cp16(Bsm + ntL * 256 + rem * 4,
                 Wp + ((size_t)(nt0 + ntL) * 128 + kb) * 64 + rem * 4);
        }
    };

    load_stage(0, 0);
    CP_COMMIT();

    for (int kt = 0; kt < 32; kt++) {
        CP_WAIT0();
        __syncthreads();
        if (kt + 1 < 32) {
            load_stage((kt + 1) & 1, (kt + 1) * 4);
            CP_COMMIT();
        }
        const uint32_t* Asm = dsm + (kt & 1) * GSTAGE2;
        const uint32_t* Bsm = Asm + ASTAGE;

#pragma unroll
        for (int ktL = 0; ktL < 4; ktL++) {
            uint32_t af[4][4];
#pragma unroll
            for (int mtL = 0; mtL < 4; mtL++) {
                uint4 t = *(const uint4*)(Asm + ((mtb + mtL) * 4 + ktL) * 128 + lane * 4);
                af[mtL][0] = t.x; af[mtL][1] = t.y; af[mtL][2] = t.z; af[mtL][3] = t.w;
            }
            uint32_t bf[8][2];
#pragma unroll
            for (int ntL = 0; ntL < 8; ntL++) {
                uint2 t = *(const uint2*)(Bsm + (ntb + ntL) * 256 + ktL * 64 + lane * 2);
                bf[ntL][0] = t.x; bf[ntL][1] = t.y;
            }
#pragma unroll
            for (int mtL = 0; mtL < 4; mtL++)
#pragma unroll
                for (int ntL = 0; ntL < 8; ntL++)
                    mma_tf32(acc[mtL][ntL], af[mtL], bf[ntL]);
        }
        __syncthreads();
    }

    const int laneA = (r << 2) | ((2 * c) & 3);
    const int laneB = (r << 2) | ((2 * c + 1) & 3);
    const int i0 = 2 * (c >> 1);

#pragma unroll
    for (int mt = 0; mt < 4; mt++) {
        int rowbase = bm + wm + mt * 16;       // multiple of 16? wm mult of 64, bm 128 -> yes
        int row0 = rowbase + r;
        int row1 = row0 + 8;
#pragma unroll
        for (int nt = 0; nt < 8; nt++) {
            int col = bn + wn + nt * 8 + c * 2;
            if (epi == 0) {
                float b0 = bias[col];
                float b1 = bias[col + 1];
                *(float2*)(C + (size_t)row0 * DOUT + col) =
                    make_float2(acc[mt][nt][0] + b0, acc[mt][nt][1] + b1);
                *(float2*)(C + (size_t)row1 * DOUT + col) =
                    make_float2(acc[mt][nt][2] + b0, acc[mt][nt][3] + b1);
            } else if (epi == 1) {
                int mtG = rowbase >> 4;
                int ktG = (bn + wn + nt * 8) >> 3;
                uint32_t* base = g_Qp + ((size_t)mtG * 128 + ktG) * 128;
                base[laneA * 4 + i0]     = f2tf32(acc[mt][nt][0]);
                base[laneB * 4 + i0]     = f2tf32(acc[mt][nt][1]);
                base[laneA * 4 + i0 + 1] = f2tf32(acc[mt][nt][2]);
                base[laneB * 4 + i0 + 1] = f2tf32(acc[mt][nt][3]);
            } else if (epi == 2) {
                // K: B-frag, n = key(row), k = dim(col)
                int ntG0 = rowbase >> 3;
                int ktG = (bn + wn + nt * 8) >> 3;
                int reg = c >> 1;
                uint32_t* b0p = g_Kp + ((size_t)ntG0 * 128 + ktG) * 64;
                uint32_t* b1p = g_Kp + ((size_t)(ntG0 + 1) * 128 + ktG) * 64;
                b0p[laneA * 2 + reg] = f2tf32(acc[mt][nt][0]);
                b0p[laneB * 2 + reg] = f2tf32(acc[mt][nt][1]);
                b1p[laneA * 2 + reg] = f2tf32(acc[mt][nt][2]);
                b1p[laneB * 2 + reg] = f2tf32(acc[mt][nt][3]);
            } else {
                // V: B-frag, n = dim(col), k = key(row)
                int ktG0 = rowbase >> 3;
                int ntG = (bn + wn + nt * 8) >> 3;
                int reg = (r < 4) ? 0 : 1;
                int l0 = ((2 * c) << 2) | (r & 3);
                int l1 = ((2 * c + 1) << 2) | (r & 3);
                uint32_t* b0p = g_Vp + ((size_t)ntG * 1024 + ktG0) * 64;
                uint32_t* b1p = g_Vp + ((size_t)ntG * 1024 + ktG0 + 1) * 64;
                b0p[l0 * 2 + reg] = f2tf32(acc[mt][nt][0]);
                b0p[l1 * 2 + reg] = f2tf32(acc[mt][nt][1]);
                b1p[l0 * 2 + reg] = f2tf32(acc[mt][nt][2]);
                b1p[l1 * 2 + reg] = f2tf32(acc[mt][nt][3]);
            }
        }
    }
}

__global__ __launch_bounds__(128, 2) void qkv_gemm_tc() {
    extern __shared__ uint32_t dsm[];
    const uint32_t* Wp = (blockIdx.z == 0) ? g_Wqp : (blockIdx.z == 1) ? g_Wkp : g_Wvp;
    gemm_body(g_Xp, Wp, nullptr, nullptr,
              blockIdx.y * 128, blockIdx.x * 128, dsm, blockIdx.z + 1);
}

__global__ __launch_bounds__(128, 2) void out_gemm_tc(const float* __restrict__ bo,
                                                      float* __restrict__ Out) {
    extern __shared__ uint32_t dsm[];
    gemm_body(g_Cp, g_Wop, Out, bo, blockIdx.y * 128, blockIdx.x * 128, dsm, 0);
}

// ---------------- tensor-core flash attention, fragment-native ---------------
// 256 thr, 8 warps; warp w = query rows [w*16, w*16+16). BQ=128, BK=64.
// smem u32: Qs 8192 | Ks 2x4096 | Vs 2x4096 | Ps 8x1024
#define ATT_SMEM_U32 32768
#define ATT_SMEM_BYTES (ATT_SMEM_U32 * 4)

__global__ __launch_bounds__(256) void attn_tc_kernel() {
    extern __shared__ uint32_t sm[];
    uint32_t* Qs = sm;
    uint32_t* Ks = sm + 8192;
    uint32_t* Vs = sm + 16384;
    uint32_t* Ps = sm + 24576;

    const int b = blockIdx.z;
    const int h = blockIdx.y;
    const int q0 = blockIdx.x * 128;
    const int len = g_len[b];
    const int tid = threadIdx.x;
    const int lane = tid & 31;
    const int wid = tid >> 5;
    const int r = lane >> 2;
    const int c = lane & 3;
    const int mt0 = (b * NN + q0) >> 4;
    const int ktH = h * 8;

    auto load_kv = [&](int s, int j0) {
        int nt0 = (b * NN + j0) >> 3;
#pragma unroll
        for (int i = 0; i < 4; i++) {
            int f = tid + i * 256;
            int blk = f >> 4, e = f & 15;
            int ntL = blk >> 3, dt = blk & 7;
            cp16(Ks + s * 4096 + blk * 64 + e * 4,
                 g_Kp + ((size_t)(nt0 + ntL) * 128 + ktH + dt) * 64 + e * 4);
        }
#pragma unroll
        for (int i = 0; i < 4; i++) {
            int f = tid + i * 256;
            int blk = f >> 4, e = f & 15;
            int dtn = blk >> 3, ktL = blk & 7;
            cp16(Vs + s * 4096 + blk * 64 + e * 4,
                 g_Vp + ((size_t)(ktH + dtn) * 1024 + nt0 + ktL) * 64 + e * 4);
        }
    };

    // prologue: Q + first KV tile
#pragma unroll
    for (int i = 0; i < 8; i++) {
        int p = tid + i * 256;
        int qt = p >> 8, rem = p & 255;
        int dt = rem >> 5, e = rem & 31;
        cp16(Qs + qt * 1024 + dt * 128 + e * 4,
             g_Qp + ((size_t)(mt0 + qt) * 128 + ktH + dt) * 128 + e * 4);
    }
    load_kv(0, 0);
    CP_COMMIT();

    float oacc[8][4];
#pragma unroll
    for (int nd = 0; nd < 8; nd++)
#pragma unroll
        for (int i = 0; i < 4; i++) oacc[nd][i] = 0.f;
    float m0 = -CUDART_INF_F, m1 = -CUDART_INF_F;
    float l0 = 0.f, l1 = 0.f;

    const int qrow0 = q0 + wid * 16 + r;
    const int qrow1 = qrow0 + 8;
    const int kv_end = min(q0 + 128, len);

    const int laneA = (r << 2) | ((2 * c) & 3);
    const int laneB = (r << 2) | ((2 * c + 1) & 3);
    const int i0 = 2 * (c >> 1);
    uint32_t* Pw = Ps + wid * 1024;

    int s = 0;
    for (int j0 = 0; j0 < kv_end; j0 += 64, s ^= 1) {
        CP_WAIT0();
        __syncthreads();
        if (j0 + 64 < kv_end) {
            load_kv(s ^ 1, j0 + 64);
            CP_COMMIT();
        }
        const uint32_t* KsS = Ks + s * 4096;
        const uint32_t* VsS = Vs + s * 4096;

        // ---- S = Q @ K^T ----
        float sacc[8][4];
#pragma unroll
        for (int nt = 0; nt < 8; nt++)
#pragma unroll
            for (int i = 0; i < 4; i++) sacc[nt][i] = 0.f;
#pragma unroll
        for (int dt = 0; dt < 8; dt++) {
            uint4 t = *(const uint4*)(Qs + wid * 1024 + dt * 128 + lane * 4);
            uint32_t af[4] = {t.x, t.y, t.z, t.w};
#pragma unroll
            for (int nt = 0; nt < 8; nt++) {
                uint2 u = *(const uint2*)(KsS + (nt * 8 + dt) * 64 + lane * 2);
                uint32_t bf[2] = {u.x, u.y};
                mma_tf32(sacc[nt], af, bf);
            }
        }

        // ---- scale + mask + online softmax ----
        float mx0 = -CUDART_INF_F, mx1 = -CUDART_INF_F;
#pragma unroll
        for (int nt = 0; nt < 8; nt++) {
            int k0i = j0 + nt * 8 + 2 * c;
            int k1i = k0i + 1;
            float s0 = sacc[nt][0] * 0.125f;
            float s1 = sacc[nt][1] * 0.125f;
            float s2 = sacc[nt][2] * 0.125f;
            float s3 = sacc[nt][3] * 0.125f;
            if (k0i > qrow0 || k0i >= len) s0 = -CUDART_INF_F;
            if (k1i > qrow0 || k1i >= len) s1 = -CUDART_INF_F;
            if (k0i > qrow1 || k0i >= len) s2 = -CUDART_INF_F;
            if (k1i > qrow1 || k1i >= len) s3 = -CUDART_INF_F;
            sacc[nt][0] = s0; sacc[nt][1] = s1; sacc[nt][2] = s2; sacc[nt][3] = s3;
            mx0 = fmaxf(mx0, fmaxf(s0, s1));
            mx1 = fmaxf(mx1, fmaxf(s2, s3));
        }
        mx0 = fmaxf(mx0, __shfl_xor_sync(0xffffffffu, mx0, 1));
        mx0 = fmaxf(mx0, __shfl_xor_sync(0xffffffffu, mx0, 2));
        mx1 = fmaxf(mx1, __shfl_xor_sync(0xffffffffu, mx1, 1));
        mx1 = fmaxf(mx1, __shfl_xor_sync(0xffffffffu, mx1, 2));

        float mn0 = fmaxf(m0, mx0);
        float mn1 = fmaxf(m1, mx1);
        float corr0 = __expf(m0 - mn0);
        float corr1 = __expf(m1 - mn1);

        float sum0 = 0.f, sum1 = 0.f;
#pragma unroll
        for (int nt = 0; nt < 8; nt++) {
            float p0 = __expf(sacc[nt][0] - mn0);
            float p1 = __expf(sacc[nt][1] - mn0);
            float p2 = __expf(sacc[nt][2] - mn1);
            float p3 = __expf(sacc[nt][3] - mn1);
            sum0 += p0 + p1;
            sum1 += p2 + p3;
            // write P in A-frag layout (warp-private block)
            Pw[nt * 128 + laneA * 4 + i0]     = f2tf32(p0);
            Pw[nt * 128 + laneB * 4 + i0]     = f2tf32(p1);
            Pw[nt * 128 + laneA * 4 + i0 + 1] = f2tf32(p2);
            Pw[nt * 128 + laneB * 4 + i0 + 1] = f2tf32(p3);
        }
        sum0 += __shfl_xor_sync(0xffffffffu, sum0, 1);
        sum0 += __shfl_xor_sync(0xffffffffu, sum0, 2);
        sum1 += __shfl_xor_sync(0xffffffffu, sum1, 1);
        sum1 += __shfl_xor_sync(0xffffffffu, sum1, 2);
        l0 = l0 * corr0 + sum0;
        l1 = l1 * corr1 + sum1;
        m0 = mn0;
        m1 = mn1;
#pragma unroll
        for (int nd = 0; nd < 8; nd++) {
            oacc[nd][0] *= corr0; oacc[nd][1] *= corr0;
            oacc[nd][2] *= corr1; oacc[nd][3] *= corr1;
        }
        __syncwarp();

        // ---- O += P @ V ----
#pragma unroll
        for (int ktL = 0; ktL < 8; ktL++) {
            uint4 t = *(const uint4*)(Pw + ktL * 128 + lane * 4);
            uint32_t af[4] = {t.x, t.y, t.z, t.w};
#pragma unroll
            for (int nd = 0; nd < 8; nd++) {
                uint2 u = *(const uint2*)(VsS + (nd * 8 + ktL) * 64 + lane * 2);
                uint32_t bf[2] = {u.x, u.y};
                mma_tf32(oacc[nd], af, bf);
            }
        }
        __syncwarp();
    }

    // ---- epilogue: A-frag tf32 into g_Cp ----
    float inv0 = 1.f / l0;
    float inv1 = 1.f / l1;
    const int mt = (b * NN + q0 + wid * 16) >> 4;
#pragma unroll
    for (int nd = 0; nd < 8; nd++) {
        int ktc = h * 8 + nd;
        uint32_t* base = g_Cp + ((size_t)mt * 128 + ktc) * 128;
        base[laneA * 4 + i0]     = f2tf32(oacc[nd][0] * inv0);
        base[laneB * 4 + i0]     = f2tf32(oacc[nd][1] * inv0);
        base[laneA * 4 + i0 + 1] = f2tf32(oacc[nd][2] * inv1);
        base[laneB * 4 + i0 + 1] = f2tf32(oacc[nd][3] * inv1);
    }
}

// ---------------- launch ------------------------------------------------------
extern "C" void kernel_launch(void* const* d_in, const int* in_sizes, int n_in,
                              void* d_out, int out_size) {
    const float* x    = (const float*)d_in[0];
    const int*   mask = (const int*)d_in[1];
    const float* Wq   = (const float*)d_in[2];
    const float* Wk   = (const float*)d_in[3];
    const float* Wv   = (const float*)d_in[4];
    const float* Wo   = (const float*)d_in[5];
    const float* bo   = (const float*)d_in[6];
    float* out = (float*)d_out;

    cudaFuncSetAttribute(attn_tc_kernel,
                         cudaFuncAttributeMaxDynamicSharedMemorySize, ATT_SMEM_BYTES);
    cudaFuncSetAttribute(qkv_gemm_tc,
                         cudaFuncAttributeMaxDynamicSharedMemorySize, GEMM_SMEM_BYTES);
    cudaFuncSetAttribute(out_gemm_tc,
                         cudaFuncAttributeMaxDynamicSharedMemorySize, GEMM_SMEM_BYTES);

    len_kernel<<<BB, 256>>>(mask);

    uint32_t* xp;
    cudaGetSymbolAddress((void**)&xp, g_Xp);
    perm_a_kernel<<<(MTOT / 16) * (DIN / 8) / 8, 256>>>(x, xp);

    dim3 gw(2048, 4);
    perm_w_kernel<<<gw, 256>>>(Wq, Wk, Wv, Wo);

    dim3 gq(DOUT / 128, MTOT / 128, 3);
    qkv_gemm_tc<<<gq, 128, GEMM_SMEM_BYTES>>>();

    dim3 ga(NN / 128, NH, BB);
    attn_tc_kernel<<<ga, 256, ATT_SMEM_BYTES>>>();

    dim3 go(DOUT / 128, MTOT / 128, 1);
    out_gemm_tc<<<go, 128, GEMM_SMEM_BYTES>>>(bo, out);
}

// round 10
// speedup vs baseline: 7.5813x; 1.0259x over previous
#include <cuda_runtime.h>
#include <cuda_bf16.h>
#include <math_constants.h>
#include <cstdint>

#define BB 4
#define NN 2048
#define DIN 1024
#define DOUT 1024
#define NH 16
#define HD 64
#define MTOT (BB * NN)

// fragment-permuted tf32 scratch
__device__ uint32_t g_Xp[MTOT * DIN];    // x   : A-frag [mtG][ktG][128]
__device__ uint32_t g_Qp[MTOT * DOUT];   // Q   : A-frag [mtG][ktG][128]
__device__ uint32_t g_Kp[MTOT * DOUT];   // K   : B-frag [ntG=key/8][ktG=dim/8][64]
__device__ uint32_t g_Vp[MTOT * DOUT];   // V   : B-frag [ntG=dim/8][ktG=key/8][64]
__device__ uint32_t g_Cp[MTOT * DOUT];   // attn out: A-frag
__device__ uint32_t g_Wqp[DIN * DOUT];   // weights: B-frag [ntG][ktG][64]
__device__ uint32_t g_Wkp[DIN * DOUT];
__device__ uint32_t g_Wvp[DIN * DOUT];
__device__ uint32_t g_Wop[DIN * DOUT];
__device__ int      g_len[BB];

// ---------------- per-batch valid length ------------------------------------
__global__ void len_kernel(const int* __restrict__ mask) {
    int b = blockIdx.x;
    int s = 0;
    for (int i = threadIdx.x; i < NN; i += 256) s += mask[b * NN + i];
    __shared__ int sh[256];
    sh[threadIdx.x] = s;
    __syncthreads();
    for (int off = 128; off; off >>= 1) {
        if (threadIdx.x < off) sh[threadIdx.x] += sh[threadIdx.x + off];
        __syncthreads();
    }
    if (threadIdx.x == 0) g_len[b] = sh[0];
}

// ---------------- helpers ----------------------------------------------------
__device__ __forceinline__ uint32_t f2tf32(float f) {
    uint32_t u;
    asm("cvt.rna.tf32.f32 %0, %1;" : "=r"(u) : "f"(f));
    return u;
}
__device__ __forceinline__ void mma_tf32(float* d, const uint32_t* a, const uint32_t* b) {
    asm volatile(
        "mma.sync.aligned.m16n8k8.row.col.f32.tf32.tf32.f32 "
        "{%0,%1,%2,%3}, {%4,%5,%6,%7}, {%8,%9}, {%0,%1,%2,%3};"
        : "+f"(d[0]), "+f"(d[1]), "+f"(d[2]), "+f"(d[3])
        : "r"(a[0]), "r"(a[1]), "r"(a[2]), "r"(a[3]), "r"(b[0]), "r"(b[1]));
}
__device__ __forceinline__ void cp16(void* s, const void* g) {
    uint32_t sa = (uint32_t)__cvta_generic_to_shared(s);
    asm volatile("cp.async.ca.shared.global [%0], [%1], 16;" :: "r"(sa), "l"(g));
}
#define CP_COMMIT() asm volatile("cp.async.commit_group;" ::: "memory")
#define CP_WAIT0()  asm volatile("cp.async.wait_group 0;" ::: "memory")
#define CP_WAIT1()  asm volatile("cp.async.wait_group 1;" ::: "memory")

// ---------------- operand permute kernels ------------------------------------
__global__ __launch_bounds__(256) void perm_a_kernel(const float* __restrict__ A,
                                                     uint32_t* __restrict__ Ap) {
    int gw = blockIdx.x * 8 + (threadIdx.x >> 5);
    int lane = threadIdx.x & 31;
    int mt = gw >> 7, kt = gw & 127;
    int r = lane >> 2, c = lane & 3;
    const float* base = A + (size_t)(mt * 16) * DIN + kt * 8;
    uint4 u;
    u.x = f2tf32(base[r * DIN + c]);
    u.y = f2tf32(base[(r + 8) * DIN + c]);
    u.z = f2tf32(base[r * DIN + c + 4]);
    u.w = f2tf32(base[(r + 8) * DIN + c + 4]);
    *(uint4*)(Ap + ((size_t)gw * 32 + lane) * 4) = u;
}

__global__ __launch_bounds__(256) void perm_w_kernel(const float* __restrict__ W0,
                                                     const float* __restrict__ W1,
                                                     const float* __restrict__ W2,
                                                     const float* __restrict__ W3) {
    const float* W = (blockIdx.y == 0) ? W0 : (blockIdx.y == 1) ? W1
                    : (blockIdx.y == 2) ? W2 : W3;
    uint32_t* Wp = (blockIdx.y == 0) ? g_Wqp : (blockIdx.y == 1) ? g_Wkp
                  : (blockIdx.y == 2) ? g_Wvp : g_Wop;
    int gw = blockIdx.x * 8 + (threadIdx.x >> 5);
    int lane = threadIdx.x & 31;
    int nt = gw >> 7, kt = gw & 127;
    int r = lane >> 2, c = lane & 3;
    uint2 u;
    u.x = f2tf32(W[(size_t)(kt * 8 + c) * DOUT + nt * 8 + r]);
    u.y = f2tf32(W[(size_t)(kt * 8 + c + 4) * DOUT + nt * 8 + r]);
    *(uint2*)(Wp + (size_t)gw * 64 + lane * 2) = u;
}

// ---------------- tf32 GEMM on permuted operands -----------------------------
// 128 threads, 4 warps 2x2, 64x64 warp tiles, tile 128x128x32.
// 3-stage cp.async pipeline, wait_group 1, one barrier per slab.
#define ASTAGE 4096
#define BSTAGE 4096
#define GSTAGE2 (ASTAGE + BSTAGE)
#define NSTAGE 3
#define GEMM_SMEM_BYTES (NSTAGE * GSTAGE2 * 4)   // 96KB

__device__ __forceinline__ void gemm_body(const uint32_t* __restrict__ Ap,
                                          const uint32_t* __restrict__ Wp,
                                          float* __restrict__ C,
                                          const float* __restrict__ bias,
                                          int bm, int bn, uint32_t* dsm, int epi) {
    const int tid = threadIdx.x;
    const int lane = tid & 31;
    const int wid = tid >> 5;
    const int wm = (wid >> 1) * 64;
    const int wn = (wid & 1) * 64;
    const int mtb = (wid >> 1) * 4;
    const int ntb = (wid & 1) * 8;
    const int r = lane >> 2;
    const int c = lane & 3;
    const int mt0 = bm >> 4;
    const int nt0 = bn >> 3;

    float acc[4][8][4];
#pragma unroll
    for (int mt = 0; mt < 4; mt++)
#pragma unroll
        for (int nt = 0; nt < 8; nt++)
#pragma unroll
            for (int i = 0; i < 4; i++) acc[mt][nt][i] = 0.f;

    auto load_stage = [&](int s, int kb) {
        uint32_t* Asm = dsm + s * GSTAGE2;
        uint32_t* Bsm = Asm + ASTAGE;
#pragma unroll
        for (int i = 0; i < 8; i++) {
            int f = tid + i * 128;
            int mtL = f >> 7, rem = f & 127;
            cp16(Asm + mtL * 512 + rem * 4,
                 Ap + ((size_t)(mt0 + mtL) * 128 + kb) * 128 + rem * 4);
        }
#pragma unroll
        for (int i = 0; i < 8; i++) {
            int f = tid + i * 128;
            int ntL = f >> 6, rem = f & 63;
            cp16(Bsm + ntL * 256 + rem * 4,
                 Wp + ((size_t)(nt0 + ntL) * 128 + kb) * 64 + rem * 4);
        }
    };

    load_stage(0, 0);
    CP_COMMIT();
    load_stage(1, 4);
    CP_COMMIT();

    int sc = 0;   // stage being computed
    for (int kt = 0; kt < 32; kt++) {
        CP_WAIT1();
        __syncthreads();
        const uint32_t* Asm = dsm + sc * GSTAGE2;
        const uint32_t* Bsm = Asm + ASTAGE;

#pragma unroll
        for (int ktL = 0; ktL < 4; ktL++) {
            uint32_t af[4][4];
#pragma unroll
            for (int mtL = 0; mtL < 4; mtL++) {
                uint4 t = *(const uint4*)(Asm + ((mtb + mtL) * 4 + ktL) * 128 + lane * 4);
                af[mtL][0] = t.x; af[mtL][1] = t.y; af[mtL][2] = t.z; af[mtL][3] = t.w;
            }
            uint32_t bf[8][2];
#pragma unroll
            for (int ntL = 0; ntL < 8; ntL++) {
                uint2 t = *(const uint2*)(Bsm + (ntb + ntL) * 256 + ktL * 64 + lane * 2);
                bf[ntL][0] = t.x; bf[ntL][1] = t.y;
            }
#pragma unroll
            for (int mtL = 0; mtL < 4; mtL++)
#pragma unroll
                for (int ntL = 0; ntL < 8; ntL++)
                    mma_tf32(acc[mtL][ntL], af[mtL], bf[ntL]);
        }

        if (kt + 2 < 32) {
            int sl = sc + 2; if (sl >= NSTAGE) sl -= NSTAGE;
            load_stage(sl, (kt + 2) * 4);
            CP_COMMIT();
        }
        sc = sc + 1; if (sc >= NSTAGE) sc = 0;
    }

    const int laneA = (r << 2) | ((2 * c) & 3);
    const int laneB = (r << 2) | ((2 * c + 1) & 3);
    const int i0 = 2 * (c >> 1);

#pragma unroll
    for (int mt = 0; mt < 4; mt++) {
        int rowbase = bm + wm + mt * 16;
        int row0 = rowbase + r;
        int row1 = row0 + 8;
#pragma unroll
        for (int nt = 0; nt < 8; nt++) {
            int col = bn + wn + nt * 8 + c * 2;
            if (epi == 0) {
                float b0 = bias[col];
                float b1 = bias[col + 1];
                *(float2*)(C + (size_t)row0 * DOUT + col) =
                    make_float2(acc[mt][nt][0] + b0, acc[mt][nt][1] + b1);
                *(float2*)(C + (size_t)row1 * DOUT + col) =
                    make_float2(acc[mt][nt][2] + b0, acc[mt][nt][3] + b1);
            } else if (epi == 1) {
                int mtG = rowbase >> 4;
                int ktG = (bn + wn + nt * 8) >> 3;
                uint32_t* base = g_Qp + ((size_t)mtG * 128 + ktG) * 128;
                base[laneA * 4 + i0]     = f2tf32(acc[mt][nt][0]);
                base[laneB * 4 + i0]     = f2tf32(acc[mt][nt][1]);
                base[laneA * 4 + i0 + 1] = f2tf32(acc[mt][nt][2]);
                base[laneB * 4 + i0 + 1] = f2tf32(acc[mt][nt][3]);
            } else if (epi == 2) {
                int ntG0 = rowbase >> 3;
                int ktG = (bn + wn + nt * 8) >> 3;
                int reg = c >> 1;
                uint32_t* b0p = g_Kp + ((size_t)ntG0 * 128 + ktG) * 64;
                uint32_t* b1p = g_Kp + ((size_t)(ntG0 + 1) * 128 + ktG) * 64;
                b0p[laneA * 2 + reg] = f2tf32(acc[mt][nt][0]);
                b0p[laneB * 2 + reg] = f2tf32(acc[mt][nt][1]);
                b1p[laneA * 2 + reg] = f2tf32(acc[mt][nt][2]);
                b1p[laneB * 2 + reg] = f2tf32(acc[mt][nt][3]);
            } else {
                int ktG0 = rowbase >> 3;
                int ntG = (bn + wn + nt * 8) >> 3;
                int reg = (r < 4) ? 0 : 1;
                int l0 = ((2 * c) << 2) | (r & 3);
                int l1 = ((2 * c + 1) << 2) | (r & 3);
                uint32_t* b0p = g_Vp + ((size_t)ntG * 1024 + ktG0) * 64;
                uint32_t* b1p = g_Vp + ((size_t)ntG * 1024 + ktG0 + 1) * 64;
                b0p[l0 * 2 + reg] = f2tf32(acc[mt][nt][0]);
                b0p[l1 * 2 + reg] = f2tf32(acc[mt][nt][1]);
                b1p[l0 * 2 + reg] = f2tf32(acc[mt][nt][2]);
                b1p[l1 * 2 + reg] = f2tf32(acc[mt][nt][3]);
            }
        }
    }
}

__global__ __launch_bounds__(128, 2) void qkv_gemm_tc() {
    extern __shared__ uint32_t dsm[];
    const uint32_t* Wp = (blockIdx.z == 0) ? g_Wqp : (blockIdx.z == 1) ? g_Wkp : g_Wvp;
    gemm_body(g_Xp, Wp, nullptr, nullptr,
              blockIdx.y * 128, blockIdx.x * 128, dsm, blockIdx.z + 1);
}

__global__ __launch_bounds__(128, 2) void out_gemm_tc(const float* __restrict__ bo,
                                                      float* __restrict__ Out) {
    extern __shared__ uint32_t dsm[];
    gemm_body(g_Cp, g_Wop, Out, bo, blockIdx.y * 128, blockIdx.x * 128, dsm, 0);
}

// ---------------- tensor-core flash attention, fragment-native ---------------
#define ATT_SMEM_U32 32768
#define ATT_SMEM_BYTES (ATT_SMEM_U32 * 4)

__global__ __launch_bounds__(256) void attn_tc_kernel() {
    extern __shared__ uint32_t sm[];
    uint32_t* Qs = sm;
    uint32_t* Ks = sm + 8192;
    uint32_t* Vs = sm + 16384;
    uint32_t* Ps = sm + 24576;

    const int b = blockIdx.z;
    const int h = blockIdx.y;
    const int q0 = blockIdx.x * 128;
    const int len = g_len[b];
    const int tid = threadIdx.x;
    const int lane = tid & 31;
    const int wid = tid >> 5;
    const int r = lane >> 2;
    const int c = lane & 3;
    const int mt0 = (b * NN + q0) >> 4;
    const int ktH = h * 8;

    auto load_kv = [&](int s, int j0) {
        int nt0 = (b * NN + j0) >> 3;
#pragma unroll
        for (int i = 0; i < 4; i++) {
            int f = tid + i * 256;
            int blk = f >> 4, e = f & 15;
            int ntL = blk >> 3, dt = blk & 7;
            cp16(Ks + s * 4096 + blk * 64 + e * 4,
                 g_Kp + ((size_t)(nt0 + ntL) * 128 + ktH + dt) * 64 + e * 4);
        }
#pragma unroll
        for (int i = 0; i < 4; i++) {
            int f = tid + i * 256;
            int blk = f >> 4, e = f & 15;
            int dtn = blk >> 3, ktL = blk & 7;
            cp16(Vs + s * 4096 + blk * 64 + e * 4,
                 g_Vp + ((size_t)(ktH + dtn) * 1024 + nt0 + ktL) * 64 + e * 4);
        }
    };

#pragma unroll
    for (int i = 0; i < 8; i++) {
        int p = tid + i * 256;
        int qt = p >> 8, rem = p & 255;
        int dt = rem >> 5, e = rem & 31;
        cp16(Qs + qt * 1024 + dt * 128 + e * 4,
             g_Qp + ((size_t)(mt0 + qt) * 128 + ktH + dt) * 128 + e * 4);
    }
    load_kv(0, 0);
    CP_COMMIT();

    float oacc[8][4];
#pragma unroll
    for (int nd = 0; nd < 8; nd++)
#pragma unroll
        for (int i = 0; i < 4; i++) oacc[nd][i] = 0.f;
    float m0 = -CUDART_INF_F, m1 = -CUDART_INF_F;
    float l0 = 0.f, l1 = 0.f;

    const int qrow0 = q0 + wid * 16 + r;
    const int qrow1 = qrow0 + 8;
    const int kv_end = min(q0 + 128, len);

    const int laneA = (r << 2) | ((2 * c) & 3);
    const int laneB = (r << 2) | ((2 * c + 1) & 3);
    const int i0 = 2 * (c >> 1);
    uint32_t* Pw = Ps + wid * 1024;

    int s = 0;
    for (int j0 = 0; j0 < kv_end; j0 += 64, s ^= 1) {
        CP_WAIT0();
        __syncthreads();
        if (j0 + 64 < kv_end) {
            load_kv(s ^ 1, j0 + 64);
            CP_COMMIT();
        }
        const uint32_t* KsS = Ks + s * 4096;
        const uint32_t* VsS = Vs + s * 4096;

        float sacc[8][4];
#pragma unroll
        for (int nt = 0; nt < 8; nt++)
#pragma unroll
            for (int i = 0; i < 4; i++) sacc[nt][i] = 0.f;
#pragma unroll
        for (int dt = 0; dt < 8; dt++) {
            uint4 t = *(const uint4*)(Qs + wid * 1024 + dt * 128 + lane * 4);
            uint32_t af[4] = {t.x, t.y, t.z, t.w};
#pragma unroll
            for (int nt = 0; nt < 8; nt++) {
                uint2 u = *(const uint2*)(KsS + (nt * 8 + dt) * 64 + lane * 2);
                uint32_t bf[2] = {u.x, u.y};
                mma_tf32(sacc[nt], af, bf);
            }
        }

        float mx0 = -CUDART_INF_F, mx1 = -CUDART_INF_F;
#pragma unroll
        for (int nt = 0; nt < 8; nt++) {
            int k0i = j0 + nt * 8 + 2 * c;
            int k1i = k0i + 1;
            float s0 = sacc[nt][0] * 0.125f;
            float s1 = sacc[nt][1] * 0.125f;
            float s2 = sacc[nt][2] * 0.125f;
            float s3 = sacc[nt][3] * 0.125f;
            if (k0i > qrow0 || k0i >= len) s0 = -CUDART_INF_F;
            if (k1i > qrow0 || k1i >= len) s1 = -CUDART_INF_F;
            if (k0i > qrow1 || k0i >= len) s2 = -CUDART_INF_F;
            if (k1i > qrow1 || k1i >= len) s3 = -CUDART_INF_F;
            sacc[nt][0] = s0; sacc[nt][1] = s1; sacc[nt][2] = s2; sacc[nt][3] = s3;
            mx0 = fmaxf(mx0, fmaxf(s0, s1));
            mx1 = fmaxf(mx1, fmaxf(s2, s3));
        }
        mx0 = fmaxf(mx0, __shfl_xor_sync(0xffffffffu, mx0, 1));
        mx0 = fmaxf(mx0, __shfl_xor_sync(0xffffffffu, mx0, 2));
        mx1 = fmaxf(mx1, __shfl_xor_sync(0xffffffffu, mx1, 1));
        mx1 = fmaxf(mx1, __shfl_xor_sync(0xffffffffu, mx1, 2));

        float mn0 = fmaxf(m0, mx0);
        float mn1 = fmaxf(m1, mx1);
        float corr0 = __expf(m0 - mn0);
        float corr1 = __expf(m1 - mn1);

        float sum0 = 0.f, sum1 = 0.f;
#pragma unroll
        for (int nt = 0; nt < 8; nt++) {
            float p0 = __expf(sacc[nt][0] - mn0);
            float p1 = __expf(sacc[nt][1] - mn0);
            float p2 = __expf(sacc[nt][2] - mn1);
            float p3 = __expf(sacc[nt][3] - mn1);
            sum0 += p0 + p1;
            sum1 += p2 + p3;
            Pw[nt * 128 + laneA * 4 + i0]     = f2tf32(p0);
            Pw[nt * 128 + laneB * 4 + i0]     = f2tf32(p1);
            Pw[nt * 128 + laneA * 4 + i0 + 1] = f2tf32(p2);
            Pw[nt * 128 + laneB * 4 + i0 + 1] = f2tf32(p3);
        }
        sum0 += __shfl_xor_sync(0xffffffffu, sum0, 1);
        sum0 += __shfl_xor_sync(0xffffffffu, sum0, 2);
        sum1 += __shfl_xor_sync(0xffffffffu, sum1, 1);
        sum1 += __shfl_xor_sync(0xffffffffu, sum1, 2);
        l0 = l0 * corr0 + sum0;
        l1 = l1 * corr1 + sum1;
        m0 = mn0;
        m1 = mn1;
#pragma unroll
        for (int nd = 0; nd < 8; nd++) {
            oacc[nd][0] *= corr0; oacc[nd][1] *= corr0;
            oacc[nd][2] *= corr1; oacc[nd][3] *= corr1;
        }
        __syncwarp();

#pragma unroll
        for (int ktL = 0; ktL < 8; ktL++) {
            uint4 t = *(const uint4*)(Pw + ktL * 128 + lane * 4);
            uint32_t af[4] = {t.x, t.y, t.z, t.w};
#pragma unroll
            for (int nd = 0; nd < 8; nd++) {
                uint2 u = *(const uint2*)(VsS + (nd * 8 + ktL) * 64 + lane * 2);
                uint32_t bf[2] = {u.x, u.y};
                mma_tf32(oacc[nd], af, bf);
            }
        }
        __syncwarp();
    }

    float inv0 = 1.f / l0;
    float inv1 = 1.f / l1;
    const int mt = (b * NN + q0 + wid * 16) >> 4;
#pragma unroll
    for (int nd = 0; nd < 8; nd++) {
        int ktc = h * 8 + nd;
        uint32_t* base = g_Cp + ((size_t)mt * 128 + ktc) * 128;
        base[laneA * 4 + i0]     = f2tf32(oacc[nd][0] * inv0);
        base[laneB * 4 + i0]     = f2tf32(oacc[nd][1] * inv0);
        base[laneA * 4 + i0 + 1] = f2tf32(oacc[nd][2] * inv1);
        base[laneB * 4 + i0 + 1] = f2tf32(oacc[nd][3] * inv1);
    }
}

// ---------------- launch ------------------------------------------------------
extern "C" void kernel_launch(void* const* d_in, const int* in_sizes, int n_in,
                              void* d_out, int out_size) {
    const float* x    = (const float*)d_in[0];
    const int*   mask = (const int*)d_in[1];
    const float* Wq   = (const float*)d_in[2];
    const float* Wk   = (const float*)d_in[3];
    const float* Wv   = (const float*)d_in[4];
    const float* Wo   = (const float*)d_in[5];
    const float* bo   = (const float*)d_in[6];
    float* out = (float*)d_out;

    cudaFuncSetAttribute(attn_tc_kernel,
                         cudaFuncAttributeMaxDynamicSharedMemorySize, ATT_SMEM_BYTES);
    cudaFuncSetAttribute(qkv_gemm_tc,
                         cudaFuncAttributeMaxDynamicSharedMemorySize, GEMM_SMEM_BYTES);
    cudaFuncSetAttribute(out_gemm_tc,
                         cudaFuncAttributeMaxDynamicSharedMemorySize, GEMM_SMEM_BYTES);

    len_kernel<<<BB, 256>>>(mask);

    uint32_t* xp;
    cudaGetSymbolAddress((void**)&xp, g_Xp);
    perm_a_kernel<<<(MTOT / 16) * (DIN / 8) / 8, 256>>>(x, xp);

    dim3 gw(2048, 4);
    perm_w_kernel<<<gw, 256>>>(Wq, Wk, Wv, Wo);

    dim3 gq(DOUT / 128, MTOT / 128, 3);
    qkv_gemm_tc<<<gq, 128, GEMM_SMEM_BYTES>>>();

    dim3 ga(NN / 128, NH, BB);
    attn_tc_kernel<<<ga, 256, ATT_SMEM_BYTES>>>();

    dim3 go(DOUT / 128, MTOT / 128, 1);
    out_gemm_tc<<<go, 128, GEMM_SMEM_BYTES>>>(bo, out);
}